// round 1
// baseline (speedup 1.0000x reference)
#include <cuda_runtime.h>

// Problem constants
constexpr int D  = 1024;   // d_model
constexpr int S  = 2048;   // sequence length
constexpr int B  = 2;      // batch
constexpr int H  = 16;     // heads
constexpr int DH = 64;     // head dim
constexpr int M  = B * S;  // 4096 rows

// Scratch (device globals; no allocations allowed)
__device__ float g_q[M * D];     // head-split [B,H,S,DH]
__device__ float g_k[M * D];     // head-split [B,H,S,DH]
__device__ float g_v[M * D];     // head-split [B,H,S,DH]
__device__ float g_att[M * D];   // [B,S,H*DH] (row-major, ready for O-proj)

// ---------------------------------------------------------------------------
// C = A[M,1024] @ W[1024,1024]^T  (both K-major / "NT" gemm)
// mode 0: write C row-major [m][n]
// mode 1: write head-split: (b,h,s,dh) layout for attention consumption
// Tile: 128x128x16, 256 threads, 8x8 micro-tile per thread.
// ---------------------------------------------------------------------------
__global__ __launch_bounds__(256, 2)
void gemm_nt(const float* __restrict__ A, const float* __restrict__ W,
             float* __restrict__ C, int mode)
{
    __shared__ float As[16 * 128];   // [k][m]
    __shared__ float Bs[16 * 128];   // [k][n]
    const int tid = threadIdx.x;
    const int tx = tid & 15;
    const int ty = tid >> 4;
    const int m0 = blockIdx.y * 128;
    const int n0 = blockIdx.x * 128;

    float acc[8][8];
#pragma unroll
    for (int i = 0; i < 8; i++)
#pragma unroll
        for (int j = 0; j < 8; j++) acc[i][j] = 0.f;

    for (int k0 = 0; k0 < D; k0 += 16) {
#pragma unroll
        for (int t = 0; t < 2; t++) {
            int idx = tid + 256 * t;      // 0..511
            int row = idx >> 2;           // 0..127
            int seg = idx & 3;            // k segment of 4
            float4 av = *(const float4*)(A + (size_t)(m0 + row) * D + k0 + seg * 4);
            As[(seg * 4 + 0) * 128 + row] = av.x;
            As[(seg * 4 + 1) * 128 + row] = av.y;
            As[(seg * 4 + 2) * 128 + row] = av.z;
            As[(seg * 4 + 3) * 128 + row] = av.w;
            float4 wv = *(const float4*)(W + (size_t)(n0 + row) * D + k0 + seg * 4);
            Bs[(seg * 4 + 0) * 128 + row] = wv.x;
            Bs[(seg * 4 + 1) * 128 + row] = wv.y;
            Bs[(seg * 4 + 2) * 128 + row] = wv.z;
            Bs[(seg * 4 + 3) * 128 + row] = wv.w;
        }
        __syncthreads();
#pragma unroll
        for (int kk = 0; kk < 16; kk++) {
            float a[8], b[8];
            float4 v;
            v = *(const float4*)(As + kk * 128 + ty * 8);     a[0]=v.x; a[1]=v.y; a[2]=v.z; a[3]=v.w;
            v = *(const float4*)(As + kk * 128 + ty * 8 + 4); a[4]=v.x; a[5]=v.y; a[6]=v.z; a[7]=v.w;
            v = *(const float4*)(Bs + kk * 128 + tx * 8);     b[0]=v.x; b[1]=v.y; b[2]=v.z; b[3]=v.w;
            v = *(const float4*)(Bs + kk * 128 + tx * 8 + 4); b[4]=v.x; b[5]=v.y; b[6]=v.z; b[7]=v.w;
#pragma unroll
            for (int i = 0; i < 8; i++)
#pragma unroll
                for (int j = 0; j < 8; j++)
                    acc[i][j] = fmaf(a[i], b[j], acc[i][j]);
        }
        __syncthreads();
    }

#pragma unroll
    for (int i = 0; i < 8; i++) {
        int m = m0 + ty * 8 + i;
        int n = n0 + tx * 8;
        if (mode == 0) {
            *(float4*)(C + (size_t)m * D + n)     = make_float4(acc[i][0], acc[i][1], acc[i][2], acc[i][3]);
            *(float4*)(C + (size_t)m * D + n + 4) = make_float4(acc[i][4], acc[i][5], acc[i][6], acc[i][7]);
        } else {
            // head-split: m = b*S + s ; n = h*DH + dh  (8 cols stay inside one head)
            int bb = m >> 11;           // m / S
            int ss = m & (S - 1);
            int hh = n >> 6;            // n / DH
            int dh = n & (DH - 1);
            float* dst = C + (((size_t)(bb * H + hh) * S + ss) * DH + dh);
            *(float4*)(dst)     = make_float4(acc[i][0], acc[i][1], acc[i][2], acc[i][3]);
            *(float4*)(dst + 4) = make_float4(acc[i][4], acc[i][5], acc[i][6], acc[i][7]);
        }
    }
}

// ---------------------------------------------------------------------------
// Flash-style attention with the reference's *naive* softmax:
//   p = exp(s/8 + mask); out = sum(p*v) / (sum(p) + 1e-10)
// One CTA = 64 query rows of one (b,h). 256 threads, 4x4 micro-tile.
// Scratch: Qs [d][m] (64x64), Ks [d][n] reused as Ps [m][k], Vs [k][d].
// ---------------------------------------------------------------------------
__global__ __launch_bounds__(256)
void flash_attn(const float* __restrict__ mask)
{
    __shared__ float Qs[64 * 64];
    __shared__ float Ks[64 * 64];
    __shared__ float Vs[64 * 64];
    const int tid = threadIdx.x;
    const int tx = tid & 15;
    const int ty = tid >> 4;
    const int bh = blockIdx.y;
    const int qb = blockIdx.x * 64;
    const float* qp = g_q + ((size_t)bh * S + qb) * DH;
    const float* kp = g_k + (size_t)bh * S * DH;
    const float* vp = g_v + (size_t)bh * S * DH;

    // Load Q transposed: Qs[d][m]
#pragma unroll
    for (int t = 0; t < 4; t++) {
        int idx = tid + 256 * t;     // 0..1023
        int row = idx >> 4;          // 0..63
        int seg = idx & 15;          // d segment of 4
        float4 v = *(const float4*)(qp + row * DH + seg * 4);
        Qs[(seg * 4 + 0) * 64 + row] = v.x;
        Qs[(seg * 4 + 1) * 64 + row] = v.y;
        Qs[(seg * 4 + 2) * 64 + row] = v.z;
        Qs[(seg * 4 + 3) * 64 + row] = v.w;
    }

    float o[4][4];
    float rs[4] = {0.f, 0.f, 0.f, 0.f};
#pragma unroll
    for (int i = 0; i < 4; i++)
#pragma unroll
        for (int j = 0; j < 4; j++) o[i][j] = 0.f;

    for (int kt = 0; kt < S / 64; kt++) {
        const int kb = kt * 64;
        __syncthreads();   // previous tile's P/V reads done before overwrite
#pragma unroll
        for (int t = 0; t < 4; t++) {
            int idx = tid + 256 * t;
            int row = idx >> 4;
            int seg = idx & 15;
            float4 kv = *(const float4*)(kp + (size_t)(kb + row) * DH + seg * 4);
            Ks[(seg * 4 + 0) * 64 + row] = kv.x;
            Ks[(seg * 4 + 1) * 64 + row] = kv.y;
            Ks[(seg * 4 + 2) * 64 + row] = kv.z;
            Ks[(seg * 4 + 3) * 64 + row] = kv.w;
            float4 vv = *(const float4*)(vp + (size_t)(kb + row) * DH + seg * 4);
            *(float4*)(Vs + row * 64 + seg * 4) = vv;
        }
        __syncthreads();

        // S = Q K^T  (4x4 per thread)
        float s[4][4];
#pragma unroll
        for (int i = 0; i < 4; i++)
#pragma unroll
            for (int j = 0; j < 4; j++) s[i][j] = 0.f;
#pragma unroll 8
        for (int d = 0; d < 64; d++) {
            float4 qv = *(const float4*)(Qs + d * 64 + ty * 4);
            float4 kv = *(const float4*)(Ks + d * 64 + tx * 4);
            float qa[4] = {qv.x, qv.y, qv.z, qv.w};
            float ka[4] = {kv.x, kv.y, kv.z, kv.w};
#pragma unroll
            for (int i = 0; i < 4; i++)
#pragma unroll
                for (int j = 0; j < 4; j++)
                    s[i][j] = fmaf(qa[i], ka[j], s[i][j]);
        }

        // scale + mask + exp, accumulate partial row sums
#pragma unroll
        for (int i = 0; i < 4; i++) {
            const float* mrow = mask + (size_t)(qb + ty * 4 + i) * S + kb + tx * 4;
#pragma unroll
            for (int j = 0; j < 4; j++) {
                float e = __expf(fmaf(s[i][j], 0.125f, mrow[j]));
                s[i][j] = e;
                rs[i] += e;
            }
        }
        __syncthreads();   // all S-compute reads of Ks finished
        // store P into Ks as [m][k]
#pragma unroll
        for (int i = 0; i < 4; i++)
            *(float4*)(Ks + (ty * 4 + i) * 64 + tx * 4) =
                make_float4(s[i][0], s[i][1], s[i][2], s[i][3]);
        __syncthreads();

        // O += P @ V
#pragma unroll 4
        for (int k = 0; k < 64; k++) {
            float4 vv = *(const float4*)(Vs + k * 64 + tx * 4);
#pragma unroll
            for (int i = 0; i < 4; i++) {
                float p = Ks[(ty * 4 + i) * 64 + k];
                o[i][0] = fmaf(p, vv.x, o[i][0]);
                o[i][1] = fmaf(p, vv.y, o[i][1]);
                o[i][2] = fmaf(p, vv.z, o[i][2]);
                o[i][3] = fmaf(p, vv.w, o[i][3]);
            }
        }
    }

    // reduce row sums across the 16 tx lanes (same ty shares a warp half)
#pragma unroll
    for (int off = 1; off < 16; off <<= 1)
#pragma unroll
        for (int i = 0; i < 4; i++)
            rs[i] += __shfl_xor_sync(0xffffffffu, rs[i], off);

    const int bb = bh >> 4;        // bh / H
    const int hh = bh & (H - 1);
#pragma unroll
    for (int i = 0; i < 4; i++) {
        int m = qb + ty * 4 + i;
        float inv = 1.f / (rs[i] + 1e-10f);
        float* dst = g_att + ((size_t)(bb * S + m)) * D + hh * DH + tx * 4;
        *(float4*)dst = make_float4(o[i][0] * inv, o[i][1] * inv,
                                    o[i][2] * inv, o[i][3] * inv);
    }
}

// ---------------------------------------------------------------------------
extern "C" void kernel_launch(void* const* d_in, const int* in_sizes, int n_in,
                              void* d_out, int out_size)
{
    (void)in_sizes; (void)n_in; (void)out_size;
    const float* x    = (const float*)d_in[0];
    const float* y    = (const float*)d_in[1];
    const float* mask = (const float*)d_in[2];
    const float* Wq   = (const float*)d_in[3];
    const float* Wk   = (const float*)d_in[4];
    const float* Wv   = (const float*)d_in[5];
    const float* Wo   = (const float*)d_in[6];
    float* out = (float*)d_out;

    float *q_ptr, *k_ptr, *v_ptr, *att_ptr;
    cudaGetSymbolAddress((void**)&q_ptr,   g_q);
    cudaGetSymbolAddress((void**)&k_ptr,   g_k);
    cudaGetSymbolAddress((void**)&v_ptr,   g_v);
    cudaGetSymbolAddress((void**)&att_ptr, g_att);

    dim3 gblk(256);
    dim3 ggrd(D / 128, M / 128);   // (8, 32)

    gemm_nt<<<ggrd, gblk>>>(y, Wq, q_ptr, 1);   // Q = y @ Wq^T (head-split)
    gemm_nt<<<ggrd, gblk>>>(x, Wk, k_ptr, 1);   // K = x @ Wk^T
    gemm_nt<<<ggrd, gblk>>>(x, Wv, v_ptr, 1);   // V = x @ Wv^T

    flash_attn<<<dim3(S / 64, B * H), 256>>>(mask);   // attention -> g_att [B,S,D]

    gemm_nt<<<ggrd, gblk>>>(att_ptr, Wo, out, 0);     // out = att @ Wo^T
}

// round 2
// speedup vs baseline: 5.0539x; 5.0539x over previous
#include <cuda_runtime.h>

// Problem constants
constexpr int D  = 1024;   // d_model
constexpr int S  = 2048;   // sequence length
constexpr int B  = 2;      // batch
constexpr int H  = 16;     // heads
constexpr int DH = 64;     // head dim
constexpr int M  = B * S;  // 4096 rows

// Scratch (device globals; no allocations allowed)
__device__ float g_q[M * D];     // head-split [B,H,S,DH]
__device__ float g_k[M * D];     // head-split [B,H,S,DH]
__device__ float g_v[M * D];     // head-split [B,H,S,DH]
__device__ float g_att[M * D];   // [B,S,H*DH] (row-major, ready for O-proj)

// ---------------------------------------------------------------------------
// helpers
// ---------------------------------------------------------------------------
__device__ __forceinline__ unsigned f2tf32(float f) {
    unsigned u;
    asm("cvt.rna.tf32.f32 %0, %1;" : "=r"(u) : "f"(f));
    return u;
}

// store float4 converted to tf32 bit patterns
__device__ __forceinline__ void st4_tf32(float* dst, float4 v) {
    uint4 u;
    u.x = f2tf32(v.x); u.y = f2tf32(v.y); u.z = f2tf32(v.z); u.w = f2tf32(v.w);
    *reinterpret_cast<uint4*>(dst) = u;
}

// D = A*B + D   (m16n8k8, tf32 inputs, f32 accum)
__device__ __forceinline__ void mma8(float c[4],
                                     unsigned a0, unsigned a1, unsigned a2, unsigned a3,
                                     unsigned b0, unsigned b1) {
    asm volatile(
        "mma.sync.aligned.m16n8k8.row.col.f32.tf32.tf32.f32 "
        "{%0,%1,%2,%3},{%4,%5,%6,%7},{%8,%9},{%0,%1,%2,%3};"
        : "+f"(c[0]), "+f"(c[1]), "+f"(c[2]), "+f"(c[3])
        : "r"(a0), "r"(a1), "r"(a2), "r"(a3), "r"(b0), "r"(b1));
}

// ---------------------------------------------------------------------------
// C = A[M,1024] @ W[1024,1024]^T via tf32 tensor cores.
// mode 0: row-major out. mode 1: head-split out (b,h,s,dh).
// Block 128x128x32, 256 thr, 8 warps (4m x 2n), warp tile 32x64.
// ---------------------------------------------------------------------------
__global__ __launch_bounds__(256, 2)
void gemm_nt(const float* __restrict__ A, const float* __restrict__ W,
             float* __restrict__ C, int mode)
{
    __shared__ float As[128 * 36];   // [m][k] pad to 36
    __shared__ float Ws[128 * 36];   // [n][k] pad to 36
    const int tid    = threadIdx.x;
    const int lane   = tid & 31;
    const int warp   = tid >> 5;
    const int warp_m = warp >> 1;    // 0..3
    const int warp_n = warp & 1;     // 0..1
    const int m0 = blockIdx.y * 128;
    const int n0 = blockIdx.x * 128;
    const int lr = lane >> 2;        // 0..7
    const int lc = lane & 3;         // 0..3

    float acc[2][8][4];
#pragma unroll
    for (int i = 0; i < 2; i++)
#pragma unroll
        for (int j = 0; j < 8; j++)
#pragma unroll
            for (int t = 0; t < 4; t++) acc[i][j][t] = 0.f;

    const unsigned* Asu = reinterpret_cast<const unsigned*>(As);
    const unsigned* Wsu = reinterpret_cast<const unsigned*>(Ws);

    for (int k0 = 0; k0 < D; k0 += 32) {
        // load A and W tiles (each 128 rows x 8 float4), convert to tf32
#pragma unroll
        for (int t = 0; t < 4; t++) {
            int idx = tid + 256 * t;       // 0..1023
            int row = idx >> 3;
            int c4  = idx & 7;
            float4 av = *(const float4*)(A + (size_t)(m0 + row) * D + k0 + c4 * 4);
            st4_tf32(&As[row * 36 + c4 * 4], av);
            float4 wv = *(const float4*)(W + (size_t)(n0 + row) * D + k0 + c4 * 4);
            st4_tf32(&Ws[row * 36 + c4 * 4], wv);
        }
        __syncthreads();

#pragma unroll
        for (int ks = 0; ks < 4; ks++) {
            const int kc = ks * 8 + lc;
            // A fragments: 2 m-tiles
            unsigned a[2][4];
#pragma unroll
            for (int mt = 0; mt < 2; mt++) {
                int r = warp_m * 32 + mt * 16 + lr;
                a[mt][0] = Asu[r * 36 + kc];
                a[mt][1] = Asu[(r + 8) * 36 + kc];
                a[mt][2] = Asu[r * 36 + kc + 4];
                a[mt][3] = Asu[(r + 8) * 36 + kc + 4];
            }
            // B fragments: 8 n-tiles
#pragma unroll
            for (int nt = 0; nt < 8; nt++) {
                int n = warp_n * 64 + nt * 8 + lr;
                unsigned b0 = Wsu[n * 36 + kc];
                unsigned b1 = Wsu[n * 36 + kc + 4];
#pragma unroll
                for (int mt = 0; mt < 2; mt++)
                    mma8(acc[mt][nt], a[mt][0], a[mt][1], a[mt][2], a[mt][3], b0, b1);
            }
        }
        __syncthreads();
    }

    // epilogue
#pragma unroll
    for (int mt = 0; mt < 2; mt++) {
#pragma unroll
        for (int nt = 0; nt < 8; nt++) {
            int rA = m0 + warp_m * 32 + mt * 16 + lr;
            int cA = n0 + warp_n * 64 + nt * 8 + 2 * lc;
#pragma unroll
            for (int half = 0; half < 2; half++) {
                int m = rA + half * 8;
                float v0 = acc[mt][nt][half * 2 + 0];
                float v1 = acc[mt][nt][half * 2 + 1];
                if (mode == 0) {
                    *(float2*)(C + (size_t)m * D + cA) = make_float2(v0, v1);
                } else {
                    int bb = m >> 11;
                    int ss = m & (S - 1);
                    int hh = cA >> 6;
                    int dh = cA & (DH - 1);
                    float* dst = C + (((size_t)(bb * H + hh) * S + ss) * DH + dh);
                    *(float2*)dst = make_float2(v0, v1);
                }
            }
        }
    }
}

// ---------------------------------------------------------------------------
// Flash attention with naive softmax, tf32 tensor cores.
// CTA = 64 q-rows of one (b,h), 4 warps (16 rows each), k-block = 64.
// ---------------------------------------------------------------------------
__global__ __launch_bounds__(128)
void flash_attn(const float* __restrict__ mask)
{
    extern __shared__ float sm[];
    float* Qs = sm;                     // 64 x 68
    float* Ks = sm + 64 * 68;           // 64 x 68
    float* Vs = sm + 2 * 64 * 68;       // 64 x 72
    float* Ps = sm + 2 * 64 * 68 + 64 * 72;  // 64 x 68

    const int tid  = threadIdx.x;
    const int lane = tid & 31;
    const int warp = tid >> 5;
    const int lr = lane >> 2;      // 0..7
    const int lc = lane & 3;       // 0..3
    const int bh = blockIdx.y;
    const int qb = blockIdx.x * 64;

    const float* qp = g_q + ((size_t)bh * S + qb) * DH;
    const float* kbase = g_k + (size_t)bh * S * DH;
    const float* vbase = g_v + (size_t)bh * S * DH;

    // load Q (64 x 64) -> tf32 smem, stride 68
#pragma unroll
    for (int t = 0; t < 8; t++) {
        int idx = tid + 128 * t;       // 0..1023
        int row = idx >> 4;
        int c4  = idx & 15;
        float4 v = *(const float4*)(qp + row * DH + c4 * 4);
        st4_tf32(&Qs[row * 68 + c4 * 4], v);
    }

    const unsigned* Qsu = reinterpret_cast<const unsigned*>(Qs);
    const unsigned* Ksu = reinterpret_cast<const unsigned*>(Ks);
    const unsigned* Vsu = reinterpret_cast<const unsigned*>(Vs);
    const unsigned* Psu = reinterpret_cast<const unsigned*>(Ps);

    const int r0 = warp * 16 + lr;     // warp-local row (of 64)

    float accO[8][4];
#pragma unroll
    for (int i = 0; i < 8; i++)
#pragma unroll
        for (int t = 0; t < 4; t++) accO[i][t] = 0.f;
    float rs0 = 0.f, rs1 = 0.f;

    for (int kb = 0; kb < S; kb += 64) {
        __syncthreads();
        // load K,V tiles
#pragma unroll
        for (int t = 0; t < 8; t++) {
            int idx = tid + 128 * t;
            int row = idx >> 4;
            int c4  = idx & 15;
            float4 kv = *(const float4*)(kbase + (size_t)(kb + row) * DH + c4 * 4);
            st4_tf32(&Ks[row * 68 + c4 * 4], kv);
            float4 vv = *(const float4*)(vbase + (size_t)(kb + row) * DH + c4 * 4);
            st4_tf32(&Vs[row * 72 + c4 * 4], vv);
        }
        __syncthreads();

        // S = Q K^T  (per warp: 16 x 64)
        float sAcc[8][4];
#pragma unroll
        for (int i = 0; i < 8; i++)
#pragma unroll
            for (int t = 0; t < 4; t++) sAcc[i][t] = 0.f;

#pragma unroll
        for (int ks = 0; ks < 8; ks++) {
            const int kc = ks * 8 + lc;
            unsigned a0 = Qsu[r0 * 68 + kc];
            unsigned a1 = Qsu[(r0 + 8) * 68 + kc];
            unsigned a2 = Qsu[r0 * 68 + kc + 4];
            unsigned a3 = Qsu[(r0 + 8) * 68 + kc + 4];
#pragma unroll
            for (int nt = 0; nt < 8; nt++) {
                int n = nt * 8 + lr;
                unsigned b0 = Ksu[n * 68 + kc];
                unsigned b1 = Ksu[n * 68 + kc + 4];
                mma8(sAcc[nt], a0, a1, a2, a3, b0, b1);
            }
        }

        // exp(scale + mask), accumulate row sums, write P (tf32) to smem
#pragma unroll
        for (int nt = 0; nt < 8; nt++) {
            int col = nt * 8 + 2 * lc;
            float2 m0v = *(const float2*)(mask + (size_t)(qb + r0) * S + kb + col);
            float2 m1v = *(const float2*)(mask + (size_t)(qb + r0 + 8) * S + kb + col);
            float e00 = __expf(fmaf(sAcc[nt][0], 0.125f, m0v.x));
            float e01 = __expf(fmaf(sAcc[nt][1], 0.125f, m0v.y));
            float e10 = __expf(fmaf(sAcc[nt][2], 0.125f, m1v.x));
            float e11 = __expf(fmaf(sAcc[nt][3], 0.125f, m1v.y));
            rs0 += e00 + e01;
            rs1 += e10 + e11;
            *(float2*)(&Ps[r0 * 68 + col]) =
                make_float2(__uint_as_float(f2tf32(e00)), __uint_as_float(f2tf32(e01)));
            *(float2*)(&Ps[(r0 + 8) * 68 + col]) =
                make_float2(__uint_as_float(f2tf32(e10)), __uint_as_float(f2tf32(e11)));
        }
        __syncwarp();

        // O += P V   (P: 16 x 64 per warp, V: 64 x 64)
#pragma unroll
        for (int kt = 0; kt < 8; kt++) {
            const int kc = kt * 8 + lc;
            unsigned a0 = Psu[r0 * 68 + kc];
            unsigned a1 = Psu[(r0 + 8) * 68 + kc];
            unsigned a2 = Psu[r0 * 68 + kc + 4];
            unsigned a3 = Psu[(r0 + 8) * 68 + kc + 4];
#pragma unroll
            for (int dt = 0; dt < 8; dt++) {
                unsigned b0 = Vsu[kc * 72 + dt * 8 + lr];
                unsigned b1 = Vsu[(kc + 4) * 72 + dt * 8 + lr];
                mma8(accO[dt], a0, a1, a2, a3, b0, b1);
            }
        }
    }

    // full row sums (columns of a row live in lanes with same lane/4)
    rs0 += __shfl_xor_sync(0xffffffffu, rs0, 1);
    rs0 += __shfl_xor_sync(0xffffffffu, rs0, 2);
    rs1 += __shfl_xor_sync(0xffffffffu, rs1, 1);
    rs1 += __shfl_xor_sync(0xffffffffu, rs1, 2);
    float inv0 = 1.f / (rs0 + 1e-10f);
    float inv1 = 1.f / (rs1 + 1e-10f);

    const int bb = bh >> 4;        // bh / H
    const int hh = bh & (H - 1);
    const int mrow0 = qb + r0;
#pragma unroll
    for (int dt = 0; dt < 8; dt++) {
        int col = hh * DH + dt * 8 + 2 * lc;
        float* dst0 = g_att + ((size_t)(bb * S + mrow0)) * D + col;
        float* dst1 = g_att + ((size_t)(bb * S + mrow0 + 8)) * D + col;
        *(float2*)dst0 = make_float2(accO[dt][0] * inv0, accO[dt][1] * inv0);
        *(float2*)dst1 = make_float2(accO[dt][2] * inv1, accO[dt][3] * inv1);
    }
}

// ---------------------------------------------------------------------------
extern "C" void kernel_launch(void* const* d_in, const int* in_sizes, int n_in,
                              void* d_out, int out_size)
{
    (void)in_sizes; (void)n_in; (void)out_size;
    const float* x    = (const float*)d_in[0];
    const float* y    = (const float*)d_in[1];
    const float* mask = (const float*)d_in[2];
    const float* Wq   = (const float*)d_in[3];
    const float* Wk   = (const float*)d_in[4];
    const float* Wv   = (const float*)d_in[5];
    const float* Wo   = (const float*)d_in[6];
    float* out = (float*)d_out;

    float *q_ptr, *k_ptr, *v_ptr, *att_ptr;
    cudaGetSymbolAddress((void**)&q_ptr,   g_q);
    cudaGetSymbolAddress((void**)&k_ptr,   g_k);
    cudaGetSymbolAddress((void**)&v_ptr,   g_v);
    cudaGetSymbolAddress((void**)&att_ptr, g_att);

    const int attn_smem = (2 * 64 * 68 + 64 * 72 + 64 * 68) * 4;   // 70656 B
    static bool attr_set = false;
    if (!attr_set) {
        cudaFuncSetAttribute(flash_attn, cudaFuncAttributeMaxDynamicSharedMemorySize,
                             attn_smem);
        attr_set = true;
    }

    dim3 gblk(256);
    dim3 ggrd(D / 128, M / 128);   // (8, 32)

    gemm_nt<<<ggrd, gblk>>>(y, Wq, q_ptr, 1);   // Q = y @ Wq^T (head-split)
    gemm_nt<<<ggrd, gblk>>>(x, Wk, k_ptr, 1);   // K = x @ Wk^T
    gemm_nt<<<ggrd, gblk>>>(x, Wv, v_ptr, 1);   // V = x @ Wv^T

    flash_attn<<<dim3(S / 64, B * H), 128, attn_smem>>>(mask);

    gemm_nt<<<ggrd, gblk>>>(att_ptr, Wo, out, 0);     // out = att @ Wo^T
}

// round 3
// speedup vs baseline: 5.1783x; 1.0246x over previous
#include <cuda_runtime.h>

// Problem constants
constexpr int D  = 1024;   // d_model
constexpr int S  = 2048;   // sequence length
constexpr int B  = 2;      // batch
constexpr int H  = 16;     // heads
constexpr int DH = 64;     // head dim
constexpr int M  = B * S;  // 4096 rows

// Scratch (device globals; no allocations allowed)
__device__ float g_q[M * D];     // head-split [B,H,S,DH]
__device__ float g_k[M * D];     // head-split [B,H,S,DH]
__device__ float g_v[M * D];     // head-split [B,H,S,DH]
__device__ float g_att[M * D];   // [B,S,H*DH] (row-major, ready for O-proj)

// ---------------------------------------------------------------------------
// helpers
// ---------------------------------------------------------------------------
__device__ __forceinline__ unsigned f2tf32(float f) {
    unsigned u;
    asm("cvt.rna.tf32.f32 %0, %1;" : "=r"(u) : "f"(f));
    return u;
}

__device__ __forceinline__ void st4_tf32(float* dst, float4 v) {
    uint4 u;
    u.x = f2tf32(v.x); u.y = f2tf32(v.y); u.z = f2tf32(v.z); u.w = f2tf32(v.w);
    *reinterpret_cast<uint4*>(dst) = u;
}

// D = A*B + D   (m16n8k8, tf32 inputs, f32 accum)
__device__ __forceinline__ void mma8(float c[4],
                                     unsigned a0, unsigned a1, unsigned a2, unsigned a3,
                                     unsigned b0, unsigned b1) {
    asm volatile(
        "mma.sync.aligned.m16n8k8.row.col.f32.tf32.tf32.f32 "
        "{%0,%1,%2,%3},{%4,%5,%6,%7},{%8,%9},{%0,%1,%2,%3};"
        : "+f"(c[0]), "+f"(c[1]), "+f"(c[2]), "+f"(c[3])
        : "r"(a0), "r"(a1), "r"(a2), "r"(a3), "r"(b0), "r"(b1));
}

// ---------------------------------------------------------------------------
// Shared GEMM body: C = A[.,1024] @ W[1024,1024]^T via tf32 tensor cores.
// mode 0: row-major out. mode 1: head-split out (b,h,s,dh).
// Block 128x128x32, 256 thr, 8 warps (4m x 2n), warp tile 32x64.
// ---------------------------------------------------------------------------
__device__ __forceinline__
void gemm_body(const float* __restrict__ A, const float* __restrict__ W,
               float* __restrict__ C, int mode, int bx, int by)
{
    __shared__ float As[128 * 36];   // [m][k] pad to 36
    __shared__ float Ws[128 * 36];   // [n][k] pad to 36
    const int tid    = threadIdx.x;
    const int lane   = tid & 31;
    const int warp   = tid >> 5;
    const int warp_m = warp >> 1;    // 0..3
    const int warp_n = warp & 1;     // 0..1
    const int m0 = by * 128;
    const int n0 = bx * 128;
    const int lr = lane >> 2;        // 0..7
    const int lc = lane & 3;         // 0..3

    float acc[2][8][4];
#pragma unroll
    for (int i = 0; i < 2; i++)
#pragma unroll
        for (int j = 0; j < 8; j++)
#pragma unroll
            for (int t = 0; t < 4; t++) acc[i][j][t] = 0.f;

    const unsigned* Asu = reinterpret_cast<const unsigned*>(As);
    const unsigned* Wsu = reinterpret_cast<const unsigned*>(Ws);

    for (int k0 = 0; k0 < D; k0 += 32) {
#pragma unroll
        for (int t = 0; t < 4; t++) {
            int idx = tid + 256 * t;       // 0..1023
            int row = idx >> 3;
            int c4  = idx & 7;
            float4 av = *(const float4*)(A + (size_t)(m0 + row) * D + k0 + c4 * 4);
            st4_tf32(&As[row * 36 + c4 * 4], av);
            float4 wv = *(const float4*)(W + (size_t)(n0 + row) * D + k0 + c4 * 4);
            st4_tf32(&Ws[row * 36 + c4 * 4], wv);
        }
        __syncthreads();

#pragma unroll
        for (int ks = 0; ks < 4; ks++) {
            const int kc = ks * 8 + lc;
            unsigned a[2][4];
#pragma unroll
            for (int mt = 0; mt < 2; mt++) {
                int r = warp_m * 32 + mt * 16 + lr;
                a[mt][0] = Asu[r * 36 + kc];
                a[mt][1] = Asu[(r + 8) * 36 + kc];
                a[mt][2] = Asu[r * 36 + kc + 4];
                a[mt][3] = Asu[(r + 8) * 36 + kc + 4];
            }
#pragma unroll
            for (int nt = 0; nt < 8; nt++) {
                int n = warp_n * 64 + nt * 8 + lr;
                unsigned b0 = Wsu[n * 36 + kc];
                unsigned b1 = Wsu[n * 36 + kc + 4];
#pragma unroll
                for (int mt = 0; mt < 2; mt++)
                    mma8(acc[mt][nt], a[mt][0], a[mt][1], a[mt][2], a[mt][3], b0, b1);
            }
        }
        __syncthreads();
    }

#pragma unroll
    for (int mt = 0; mt < 2; mt++) {
#pragma unroll
        for (int nt = 0; nt < 8; nt++) {
            int rA = m0 + warp_m * 32 + mt * 16 + lr;
            int cA = n0 + warp_n * 64 + nt * 8 + 2 * lc;
#pragma unroll
            for (int half = 0; half < 2; half++) {
                int m = rA + half * 8;
                float v0 = acc[mt][nt][half * 2 + 0];
                float v1 = acc[mt][nt][half * 2 + 1];
                if (mode == 0) {
                    *(float2*)(C + (size_t)m * D + cA) = make_float2(v0, v1);
                } else {
                    int bb = m >> 11;
                    int ss = m & (S - 1);
                    int hh = cA >> 6;
                    int dh = cA & (DH - 1);
                    float* dst = C + (((size_t)(bb * H + hh) * S + ss) * DH + dh);
                    *(float2*)dst = make_float2(v0, v1);
                }
            }
        }
    }
}

// Fused Q/K/V projections: grid.z selects which projection.
__global__ __launch_bounds__(256, 2)
void qkv_gemm(const float* __restrict__ x, const float* __restrict__ y,
              const float* __restrict__ Wq, const float* __restrict__ Wk,
              const float* __restrict__ Wv)
{
    const float* A; const float* W; float* C;
    if (blockIdx.z == 0)      { A = y; W = Wq; C = g_q; }
    else if (blockIdx.z == 1) { A = x; W = Wk; C = g_k; }
    else                      { A = x; W = Wv; C = g_v; }
    gemm_body(A, W, C, 1, blockIdx.x, blockIdx.y);
}

// Output projection.
__global__ __launch_bounds__(256, 2)
void o_gemm(const float* __restrict__ Att, const float* __restrict__ Wo,
            float* __restrict__ Out)
{
    gemm_body(Att, Wo, Out, 0, blockIdx.x, blockIdx.y);
}

// ---------------------------------------------------------------------------
// Flash attention, naive softmax, tf32 tensor cores.
// CTA = 128 q-rows of one (b,h), 256 thr / 8 warps (16 rows each), k-tile 64.
// Q fragments live in registers across the whole K loop.
// smem: K 64x68, V 64x72, P 128x68 (Q staged through P region once).
// ---------------------------------------------------------------------------
constexpr int ATTN_SMEM = (64 * 68 + 64 * 72 + 128 * 68) * 4;   // 70656 B

__global__ __launch_bounds__(256, 2)
void flash_attn(const float* __restrict__ mask)
{
    extern __shared__ float sm[];
    float* Ks = sm;                      // 64 x 68
    float* Vs = sm + 64 * 68;            // 64 x 72
    float* Ps = sm + 64 * 68 + 64 * 72;  // 128 x 68 (also Q staging)

    const int tid  = threadIdx.x;
    const int lane = tid & 31;
    const int warp = tid >> 5;
    const int lr = lane >> 2;      // 0..7
    const int lc = lane & 3;       // 0..3
    const int bh = blockIdx.y;
    const int qb = blockIdx.x * 128;

    const float* qp    = g_q + ((size_t)bh * S + qb) * DH;
    const float* kbase = g_k + (size_t)bh * S * DH;
    const float* vbase = g_v + (size_t)bh * S * DH;

    // Stage Q (128 x 64) -> tf32 in Ps (stride 68)
#pragma unroll
    for (int t = 0; t < 8; t++) {
        int idx = tid + 256 * t;       // 0..2047
        int row = idx >> 4;
        int c4  = idx & 15;
        float4 v = *(const float4*)(qp + row * DH + c4 * 4);
        st4_tf32(&Ps[row * 68 + c4 * 4], v);
    }
    __syncthreads();

    const unsigned* Psu = reinterpret_cast<const unsigned*>(Ps);
    const unsigned* Ksu = reinterpret_cast<const unsigned*>(Ks);
    const unsigned* Vsu = reinterpret_cast<const unsigned*>(Vs);
    const int r0 = warp * 16 + lr;       // warp-local q row (of 128)

    // Q fragments in registers for the entire loop (warp reads only its own
    // 16-row P slice; P stores later also touch only that slice -> no hazard).
    unsigned qf[8][4];
#pragma unroll
    for (int ks = 0; ks < 8; ks++) {
        const int kc = ks * 8 + lc;
        qf[ks][0] = Psu[r0 * 68 + kc];
        qf[ks][1] = Psu[(r0 + 8) * 68 + kc];
        qf[ks][2] = Psu[r0 * 68 + kc + 4];
        qf[ks][3] = Psu[(r0 + 8) * 68 + kc + 4];
    }

    float accO[8][4];
#pragma unroll
    for (int i = 0; i < 8; i++)
#pragma unroll
        for (int t = 0; t < 4; t++) accO[i][t] = 0.f;
    float rs0 = 0.f, rs1 = 0.f;

    for (int kb = 0; kb < S; kb += 64) {
        __syncthreads();   // prior iter's K/V reads complete
        // load K,V tile (64 rows x 16 float4), cvt to tf32
#pragma unroll
        for (int t = 0; t < 4; t++) {
            int idx = tid + 256 * t;   // 0..1023
            int row = idx >> 4;
            int c4  = idx & 15;
            float4 kv = *(const float4*)(kbase + (size_t)(kb + row) * DH + c4 * 4);
            st4_tf32(&Ks[row * 68 + c4 * 4], kv);
            float4 vv = *(const float4*)(vbase + (size_t)(kb + row) * DH + c4 * 4);
            st4_tf32(&Vs[row * 72 + c4 * 4], vv);
        }
        __syncthreads();

        // S = Q K^T  (warp: 16 x 64)
        float sAcc[8][4];
#pragma unroll
        for (int i = 0; i < 8; i++)
#pragma unroll
            for (int t = 0; t < 4; t++) sAcc[i][t] = 0.f;
#pragma unroll
        for (int ks = 0; ks < 8; ks++) {
            const int kc = ks * 8 + lc;
#pragma unroll
            for (int nt = 0; nt < 8; nt++) {
                int n = nt * 8 + lr;
                unsigned b0 = Ksu[n * 68 + kc];
                unsigned b1 = Ksu[n * 68 + kc + 4];
                mma8(sAcc[nt], qf[ks][0], qf[ks][1], qf[ks][2], qf[ks][3], b0, b1);
            }
        }

        // exp(scale + mask), accumulate row sums, write P (tf32) to smem
#pragma unroll
        for (int nt = 0; nt < 8; nt++) {
            int col = nt * 8 + 2 * lc;
            float2 m0v = *(const float2*)(mask + (size_t)(qb + r0) * S + kb + col);
            float2 m1v = *(const float2*)(mask + (size_t)(qb + r0 + 8) * S + kb + col);
            float e00 = __expf(fmaf(sAcc[nt][0], 0.125f, m0v.x));
            float e01 = __expf(fmaf(sAcc[nt][1], 0.125f, m0v.y));
            float e10 = __expf(fmaf(sAcc[nt][2], 0.125f, m1v.x));
            float e11 = __expf(fmaf(sAcc[nt][3], 0.125f, m1v.y));
            rs0 += e00 + e01;
            rs1 += e10 + e11;
            *(float2*)(&Ps[r0 * 68 + col]) =
                make_float2(__uint_as_float(f2tf32(e00)), __uint_as_float(f2tf32(e01)));
            *(float2*)(&Ps[(r0 + 8) * 68 + col]) =
                make_float2(__uint_as_float(f2tf32(e10)), __uint_as_float(f2tf32(e11)));
        }
        __syncwarp();

        // O += P V   (P: warp's 16 x 64, V: 64 x 64)
#pragma unroll
        for (int kt = 0; kt < 8; kt++) {
            const int kc = kt * 8 + lc;
            unsigned a0 = Psu[r0 * 68 + kc];
            unsigned a1 = Psu[(r0 + 8) * 68 + kc];
            unsigned a2 = Psu[r0 * 68 + kc + 4];
            unsigned a3 = Psu[(r0 + 8) * 68 + kc + 4];
#pragma unroll
            for (int dt = 0; dt < 8; dt++) {
                unsigned b0 = Vsu[kc * 72 + dt * 8 + lr];
                unsigned b1 = Vsu[(kc + 4) * 72 + dt * 8 + lr];
                mma8(accO[dt], a0, a1, a2, a3, b0, b1);
            }
        }
    }

    // full row sums (cols of a row live in the 4 lanes of a quad)
    rs0 += __shfl_xor_sync(0xffffffffu, rs0, 1);
    rs0 += __shfl_xor_sync(0xffffffffu, rs0, 2);
    rs1 += __shfl_xor_sync(0xffffffffu, rs1, 1);
    rs1 += __shfl_xor_sync(0xffffffffu, rs1, 2);
    float inv0 = 1.f / (rs0 + 1e-10f);
    float inv1 = 1.f / (rs1 + 1e-10f);

    const int bb = bh >> 4;        // bh / H
    const int hh = bh & (H - 1);
    const int mrow0 = qb + r0;
#pragma unroll
    for (int dt = 0; dt < 8; dt++) {
        int col = hh * DH + dt * 8 + 2 * lc;
        float* dst0 = g_att + ((size_t)(bb * S + mrow0)) * D + col;
        float* dst1 = g_att + ((size_t)(bb * S + mrow0 + 8)) * D + col;
        *(float2*)dst0 = make_float2(accO[dt][0] * inv0, accO[dt][1] * inv0);
        *(float2*)dst1 = make_float2(accO[dt][2] * inv1, accO[dt][3] * inv1);
    }
}

// ---------------------------------------------------------------------------
extern "C" void kernel_launch(void* const* d_in, const int* in_sizes, int n_in,
                              void* d_out, int out_size)
{
    (void)in_sizes; (void)n_in; (void)out_size;
    const float* x    = (const float*)d_in[0];
    const float* y    = (const float*)d_in[1];
    const float* mask = (const float*)d_in[2];
    const float* Wq   = (const float*)d_in[3];
    const float* Wk   = (const float*)d_in[4];
    const float* Wv   = (const float*)d_in[5];
    const float* Wo   = (const float*)d_in[6];
    float* out = (float*)d_out;

    float* att_ptr;
    cudaGetSymbolAddress((void**)&att_ptr, g_att);

    static bool attr_set = false;
    if (!attr_set) {
        cudaFuncSetAttribute(flash_attn, cudaFuncAttributeMaxDynamicSharedMemorySize,
                             ATTN_SMEM);
        attr_set = true;
    }

    qkv_gemm<<<dim3(D / 128, M / 128, 3), 256>>>(x, y, Wq, Wk, Wv);
    flash_attn<<<dim3(S / 128, B * H), 256, ATTN_SMEM>>>(mask);
    o_gemm<<<dim3(D / 128, M / 128), 256>>>(att_ptr, Wo, out);
}

// round 7
// speedup vs baseline: 5.3114x; 1.0257x over previous
#include <cuda_runtime.h>
#include <cstdint>

// Problem constants
constexpr int D  = 1024;   // d_model
constexpr int S  = 2048;   // sequence length
constexpr int B  = 2;      // batch
constexpr int H  = 16;     // heads
constexpr int DH = 64;     // head dim
constexpr int M  = B * S;  // 4096 rows

// Scratch (device globals; no allocations allowed)
__device__ float g_x[M * D];     // x in tf32 bits
__device__ float g_y[M * D];     // y in tf32 bits
__device__ float g_wq[D * D];    // weights in tf32 bits
__device__ float g_wk[D * D];
__device__ float g_wv[D * D];
__device__ float g_wo[D * D];
__device__ float g_q[M * D];     // head-split [B,H,S,DH], tf32 bits
__device__ float g_k[M * D];
__device__ float g_v[M * D];
__device__ float g_att[M * D];   // [B,S,H*DH], tf32 bits

// ---------------------------------------------------------------------------
// helpers
// ---------------------------------------------------------------------------
__device__ __forceinline__ unsigned f2tf32(float f) {
    unsigned u;
    asm("cvt.rna.tf32.f32 %0, %1;" : "=r"(u) : "f"(f));
    return u;
}

__device__ __forceinline__ void cp16(const void* smem_dst, const void* gmem_src) {
    unsigned d = (unsigned)__cvta_generic_to_shared(smem_dst);
    asm volatile("cp.async.cg.shared.global [%0], [%1], 16;" :: "r"(d), "l"(gmem_src));
}
__device__ __forceinline__ void cp_commit() {
    asm volatile("cp.async.commit_group;");
}
__device__ __forceinline__ void cp_wait0() {
    asm volatile("cp.async.wait_group 0;");
}
__device__ __forceinline__ void cp_wait1() {
    asm volatile("cp.async.wait_group 1;");
}

// D = A*B + D   (m16n8k8, tf32 inputs, f32 accum)
__device__ __forceinline__ void mma8(float c[4],
                                     unsigned a0, unsigned a1, unsigned a2, unsigned a3,
                                     unsigned b0, unsigned b1) {
    asm volatile(
        "mma.sync.aligned.m16n8k8.row.col.f32.tf32.tf32.f32 "
        "{%0,%1,%2,%3},{%4,%5,%6,%7},{%8,%9},{%0,%1,%2,%3};"
        : "+f"(c[0]), "+f"(c[1]), "+f"(c[2]), "+f"(c[3])
        : "r"(a0), "r"(a1), "r"(a2), "r"(a3), "r"(b0), "r"(b1));
}

// ---------------------------------------------------------------------------
// Elementwise tf32 conversion (fp32 -> tf32 bit pattern)
// ---------------------------------------------------------------------------
__global__ void cvt_tf32(const float4* __restrict__ src, float4* __restrict__ dst, int n4)
{
    for (int i = blockIdx.x * blockDim.x + threadIdx.x; i < n4;
         i += gridDim.x * blockDim.x) {
        float4 v = src[i];
        uint4 u;
        u.x = f2tf32(v.x); u.y = f2tf32(v.y); u.z = f2tf32(v.z); u.w = f2tf32(v.w);
        reinterpret_cast<uint4*>(dst)[i] = u;
    }
}

// ---------------------------------------------------------------------------
// GEMM: C = A[.,1024] @ W[1024,1024]^T, tf32 mma, cp.async 2-stage pipeline.
// Inputs already tf32 bit patterns. Block 128x128x32, 256 thr, 8 warps.
// mode 0: row-major fp32 out. mode 1: head-split tf32 out.
// ---------------------------------------------------------------------------
constexpr int GTILE = 128 * 36;                 // floats per (matrix,stage)
constexpr int GEMM_SMEM = 4 * GTILE * 4;        // 73728 B

__device__ __forceinline__
void gemm_load(const float* __restrict__ A, const float* __restrict__ W,
               float* As, float* Ws, int m0, int n0, int k0, int tid)
{
#pragma unroll
    for (int t = 0; t < 4; t++) {
        int idx = tid + 256 * t;       // 0..1023
        int row = idx >> 3;
        int c4  = idx & 7;
        cp16(As + row * 36 + c4 * 4, A + (size_t)(m0 + row) * D + k0 + c4 * 4);
        cp16(Ws + row * 36 + c4 * 4, W + (size_t)(n0 + row) * D + k0 + c4 * 4);
    }
}

__device__ __forceinline__
void gemm_body(const float* __restrict__ A, const float* __restrict__ W,
               float* __restrict__ C, int mode, int bx, int by)
{
    extern __shared__ float smg[];
    // layout: As[stage] = smg + s*GTILE ; Ws[stage] = smg + 2*GTILE + s*GTILE
    const int tid    = threadIdx.x;
    const int lane   = tid & 31;
    const int warp   = tid >> 5;
    const int warp_m = warp >> 1;    // 0..3
    const int warp_n = warp & 1;     // 0..1
    const int m0 = by * 128;
    const int n0 = bx * 128;
    const int lr = lane >> 2;        // 0..7
    const int lc = lane & 3;         // 0..3

    float acc[2][8][4];
#pragma unroll
    for (int i = 0; i < 2; i++)
#pragma unroll
        for (int j = 0; j < 8; j++)
#pragma unroll
            for (int t = 0; t < 4; t++) acc[i][j][t] = 0.f;

    gemm_load(A, W, smg, smg + 2 * GTILE, m0, n0, 0, tid);
    cp_commit();

    for (int kt = 0; kt < 32; kt++) {
        const int s = kt & 1;
        if (kt < 31) {
            gemm_load(A, W, smg + (s ^ 1) * GTILE, smg + 2 * GTILE + (s ^ 1) * GTILE,
                      m0, n0, (kt + 1) * 32, tid);
            cp_commit();
            cp_wait1();
        } else {
            cp_wait0();
        }
        __syncthreads();

        const unsigned* Asu = reinterpret_cast<const unsigned*>(smg + s * GTILE);
        const unsigned* Wsu = reinterpret_cast<const unsigned*>(smg + 2 * GTILE + s * GTILE);

#pragma unroll
        for (int ks = 0; ks < 4; ks++) {
            const int kc = ks * 8 + lc;
            unsigned a[2][4];
#pragma unroll
            for (int mt = 0; mt < 2; mt++) {
                int r = warp_m * 32 + mt * 16 + lr;
                a[mt][0] = Asu[r * 36 + kc];
                a[mt][1] = Asu[(r + 8) * 36 + kc];
                a[mt][2] = Asu[r * 36 + kc + 4];
                a[mt][3] = Asu[(r + 8) * 36 + kc + 4];
            }
#pragma unroll
            for (int nt = 0; nt < 8; nt++) {
                int n = warp_n * 64 + nt * 8 + lr;
                unsigned b0 = Wsu[n * 36 + kc];
                unsigned b1 = Wsu[n * 36 + kc + 4];
#pragma unroll
                for (int mt = 0; mt < 2; mt++)
                    mma8(acc[mt][nt], a[mt][0], a[mt][1], a[mt][2], a[mt][3], b0, b1);
            }
        }
        __syncthreads();
    }

#pragma unroll
    for (int mt = 0; mt < 2; mt++) {
#pragma unroll
        for (int nt = 0; nt < 8; nt++) {
            int rA = m0 + warp_m * 32 + mt * 16 + lr;
            int cA = n0 + warp_n * 64 + nt * 8 + 2 * lc;
#pragma unroll
            for (int half = 0; half < 2; half++) {
                int m = rA + half * 8;
                float v0 = acc[mt][nt][half * 2 + 0];
                float v1 = acc[mt][nt][half * 2 + 1];
                if (mode == 0) {
                    *(float2*)(C + (size_t)m * D + cA) = make_float2(v0, v1);
                } else {
                    int bb = m >> 11;
                    int ss = m & (S - 1);
                    int hh = cA >> 6;
                    int dh = cA & (DH - 1);
                    float* dst = C + (((size_t)(bb * H + hh) * S + ss) * DH + dh);
                    *(float2*)dst = make_float2(__uint_as_float(f2tf32(v0)),
                                                __uint_as_float(f2tf32(v1)));
                }
            }
        }
    }
}

__global__ __launch_bounds__(256, 2)
void qkv_gemm()
{
    const float* A; const float* W; float* C;
    if (blockIdx.z == 0)      { A = g_y; W = g_wq; C = g_q; }
    else if (blockIdx.z == 1) { A = g_x; W = g_wk; C = g_k; }
    else                      { A = g_x; W = g_wv; C = g_v; }
    gemm_body(A, W, C, 1, blockIdx.x, blockIdx.y);
}

__global__ __launch_bounds__(256, 2)
void o_gemm(float* __restrict__ Out)
{
    gemm_body(g_att, g_wo, Out, 0, blockIdx.x, blockIdx.y);
}

// ---------------------------------------------------------------------------
// Flash attention, naive softmax, tf32 mma, cp.async double-buffered K/V.
// CTA = 128 q-rows of one (b,h), 256 thr / 8 warps, k-tile 64.
// smem: K 2x64x68, V 2x64x72, P 128x68 (Q staged through P once).
// ---------------------------------------------------------------------------
constexpr int KTILE = 64 * 68;   // floats
constexpr int VTILE = 64 * 72;
constexpr int ATTN_SMEM = (2 * KTILE + 2 * VTILE + 128 * 68) * 4;   // 106496 B

__device__ __forceinline__
void kv_load(const float* kbase, const float* vbase, float* Kd, float* Vd,
             int kb, int tid)
{
#pragma unroll
    for (int t = 0; t < 4; t++) {
        int idx = tid + 256 * t;   // 0..1023
        int row = idx >> 4;
        int c4  = idx & 15;
        cp16(Kd + row * 68 + c4 * 4, kbase + (size_t)(kb + row) * DH + c4 * 4);
        cp16(Vd + row * 72 + c4 * 4, vbase + (size_t)(kb + row) * DH + c4 * 4);
    }
}

__global__ __launch_bounds__(256, 2)
void flash_attn(const float* __restrict__ mask)
{
    extern __shared__ float sm[];
    float* Ks2 = sm;                         // 2 stages of 64x68
    float* Vs2 = sm + 2 * KTILE;             // 2 stages of 64x72
    float* Ps  = sm + 2 * KTILE + 2 * VTILE; // 128 x 68 (Q staging, then P)

    const int tid  = threadIdx.x;
    const int lane = tid & 31;
    const int warp = tid >> 5;
    const int lr = lane >> 2;      // 0..7
    const int lc = lane & 3;       // 0..3
    const int bh = blockIdx.y;
    const int qb = blockIdx.x * 128;

    const float* qp    = g_q + ((size_t)bh * S + qb) * DH;
    const float* kbase = g_k + (size_t)bh * S * DH;
    const float* vbase = g_v + (size_t)bh * S * DH;

    // Stage Q (128 x 64, already tf32) into Ps via cp.async
#pragma unroll
    for (int t = 0; t < 8; t++) {
        int idx = tid + 256 * t;       // 0..2047
        int row = idx >> 4;
        int c4  = idx & 15;
        cp16(&Ps[row * 68 + c4 * 4], qp + (size_t)row * DH + c4 * 4);
    }
    cp_commit();
    kv_load(kbase, vbase, Ks2, Vs2, 0, tid);   // KV tile 0 -> stage 0
    cp_commit();
    cp_wait1();            // Q complete (KV0 may still be in flight)
    __syncthreads();

    const unsigned* Psu = reinterpret_cast<const unsigned*>(Ps);
    const int r0 = warp * 16 + lr;       // warp-local q row (of 128)

    // Q fragments in registers for the whole loop
    unsigned qf[8][4];
#pragma unroll
    for (int ks = 0; ks < 8; ks++) {
        const int kc = ks * 8 + lc;
        qf[ks][0] = Psu[r0 * 68 + kc];
        qf[ks][1] = Psu[(r0 + 8) * 68 + kc];
        qf[ks][2] = Psu[r0 * 68 + kc + 4];
        qf[ks][3] = Psu[(r0 + 8) * 68 + kc + 4];
    }

    float accO[8][4];
#pragma unroll
    for (int i = 0; i < 8; i++)
#pragma unroll
        for (int t = 0; t < 4; t++) accO[i][t] = 0.f;
    float rs0 = 0.f, rs1 = 0.f;

    for (int kt = 0; kt < S / 64; kt++) {
        const int s = kt & 1;
        if (kt < S / 64 - 1) {
            kv_load(kbase, vbase, Ks2 + (s ^ 1) * KTILE, Vs2 + (s ^ 1) * VTILE,
                    (kt + 1) * 64, tid);
            cp_commit();
            cp_wait1();     // KV[kt] done, KV[kt+1] in flight
        } else {
            cp_wait0();
        }
        __syncthreads();    // KV[kt] visible to all; prior-stage reads done

        const unsigned* Ksu = reinterpret_cast<const unsigned*>(Ks2 + s * KTILE);
        const unsigned* Vsu = reinterpret_cast<const unsigned*>(Vs2 + s * VTILE);
        const int kb = kt * 64;

        // S = Q K^T  (warp: 16 x 64)
        float sAcc[8][4];
#pragma unroll
        for (int i = 0; i < 8; i++)
#pragma unroll
            for (int t = 0; t < 4; t++) sAcc[i][t] = 0.f;
#pragma unroll
        for (int ks = 0; ks < 8; ks++) {
            const int kc = ks * 8 + lc;
#pragma unroll
            for (int nt = 0; nt < 8; nt++) {
                int n = nt * 8 + lr;
                unsigned b0 = Ksu[n * 68 + kc];
                unsigned b1 = Ksu[n * 68 + kc + 4];
                mma8(sAcc[nt], qf[ks][0], qf[ks][1], qf[ks][2], qf[ks][3], b0, b1);
            }
        }

        // exp(scale + mask), accumulate row sums, write P (tf32) to smem
#pragma unroll
        for (int nt = 0; nt < 8; nt++) {
            int col = nt * 8 + 2 * lc;
            float2 m0v = *(const float2*)(mask + (size_t)(qb + r0) * S + kb + col);
            float2 m1v = *(const float2*)(mask + (size_t)(qb + r0 + 8) * S + kb + col);
            float e00 = __expf(fmaf(sAcc[nt][0], 0.125f, m0v.x));
            float e01 = __expf(fmaf(sAcc[nt][1], 0.125f, m0v.y));
            float e10 = __expf(fmaf(sAcc[nt][2], 0.125f, m1v.x));
            float e11 = __expf(fmaf(sAcc[nt][3], 0.125f, m1v.y));
            rs0 += e00 + e01;
            rs1 += e10 + e11;
            *(float2*)(&Ps[r0 * 68 + col]) =
                make_float2(__uint_as_float(f2tf32(e00)), __uint_as_float(f2tf32(e01)));
            *(float2*)(&Ps[(r0 + 8) * 68 + col]) =
                make_float2(__uint_as_float(f2tf32(e10)), __uint_as_float(f2tf32(e11)));
        }
        __syncwarp();

        // O += P V   (P: warp's 16 x 64, V: 64 x 64)
#pragma unroll
        for (int ktc = 0; ktc < 8; ktc++) {
            const int kc = ktc * 8 + lc;
            unsigned a0 = Psu[r0 * 68 + kc];
            unsigned a1 = Psu[(r0 + 8) * 68 + kc];
            unsigned a2 = Psu[r0 * 68 + kc + 4];
            unsigned a3 = Psu[(r0 + 8) * 68 + kc + 4];
#pragma unroll
            for (int dt = 0; dt < 8; dt++) {
                unsigned b0 = Vsu[kc * 72 + dt * 8 + lr];
                unsigned b1 = Vsu[(kc + 4) * 72 + dt * 8 + lr];
                mma8(accO[dt], a0, a1, a2, a3, b0, b1);
            }
        }
        __syncthreads();    // stage-s reads done before next prefetch writes it
    }

    // full row sums (cols of a row live in the 4 lanes of a quad)
    rs0 += __shfl_xor_sync(0xffffffffu, rs0, 1);
    rs0 += __shfl_xor_sync(0xffffffffu, rs0, 2);
    rs1 += __shfl_xor_sync(0xffffffffu, rs1, 1);
    rs1 += __shfl_xor_sync(0xffffffffu, rs1, 2);
    float inv0 = 1.f / (rs0 + 1e-10f);
    float inv1 = 1.f / (rs1 + 1e-10f);

    const int bb = bh >> 4;        // bh / H
    const int hh = bh & (H - 1);
    const int mrow0 = qb + r0;
#pragma unroll
    for (int dt = 0; dt < 8; dt++) {
        int col = hh * DH + dt * 8 + 2 * lc;
        float* dst0 = g_att + ((size_t)(bb * S + mrow0)) * D + col;
        float* dst1 = g_att + ((size_t)(bb * S + mrow0 + 8)) * D + col;
        *(float2*)dst0 = make_float2(__uint_as_float(f2tf32(accO[dt][0] * inv0)),
                                     __uint_as_float(f2tf32(accO[dt][1] * inv0)));
        *(float2*)dst1 = make_float2(__uint_as_float(f2tf32(accO[dt][2] * inv1)),
                                     __uint_as_float(f2tf32(accO[dt][3] * inv1)));
    }
}

// ---------------------------------------------------------------------------
extern "C" void kernel_launch(void* const* d_in, const int* in_sizes, int n_in,
                              void* d_out, int out_size)
{
    (void)in_sizes; (void)n_in; (void)out_size;
    const float* x    = (const float*)d_in[0];
    const float* y    = (const float*)d_in[1];
    const float* mask = (const float*)d_in[2];
    const float* Wq   = (const float*)d_in[3];
    const float* Wk   = (const float*)d_in[4];
    const float* Wv   = (const float*)d_in[5];
    const float* Wo   = (const float*)d_in[6];
    float* out = (float*)d_out;

    float *px, *py, *pwq, *pwk, *pwv, *pwo;
    cudaGetSymbolAddress((void**)&px,  g_x);
    cudaGetSymbolAddress((void**)&py,  g_y);
    cudaGetSymbolAddress((void**)&pwq, g_wq);
    cudaGetSymbolAddress((void**)&pwk, g_wk);
    cudaGetSymbolAddress((void**)&pwv, g_wv);
    cudaGetSymbolAddress((void**)&pwo, g_wo);

    static bool attr_set = false;
    if (!attr_set) {
        cudaFuncSetAttribute(flash_attn, cudaFuncAttributeMaxDynamicSharedMemorySize,
                             ATTN_SMEM);
        cudaFuncSetAttribute(qkv_gemm, cudaFuncAttributeMaxDynamicSharedMemorySize,
                             GEMM_SMEM);
        cudaFuncSetAttribute(o_gemm, cudaFuncAttributeMaxDynamicSharedMemorySize,
                             GEMM_SMEM);
        attr_set = true;
    }

    // tf32 conversion passes
    cvt_tf32<<<2048, 256>>>((const float4*)x,  (float4*)px,  M * D / 4);
    cvt_tf32<<<2048, 256>>>((const float4*)y,  (float4*)py,  M * D / 4);
    cvt_tf32<<<1024, 256>>>((const float4*)Wq, (float4*)pwq, D * D / 4);
    cvt_tf32<<<1024, 256>>>((const float4*)Wk, (float4*)pwk, D * D / 4);
    cvt_tf32<<<1024, 256>>>((const float4*)Wv, (float4*)pwv, D * D / 4);
    cvt_tf32<<<1024, 256>>>((const float4*)Wo, (float4*)pwo, D * D / 4);

    qkv_gemm<<<dim3(D / 128, M / 128, 3), 256, GEMM_SMEM>>>();
    flash_attn<<<dim3(S / 128, B * H), 256, ATTN_SMEM>>>(mask);
    o_gemm<<<dim3(D / 128, M / 128), 256, GEMM_SMEM>>>(out);
}

// round 9
// speedup vs baseline: 9.6079x; 1.8089x over previous
#include <cuda_runtime.h>
#include <cuda_fp16.h>
#include <cstdint>

// Problem constants
constexpr int D  = 1024;   // d_model
constexpr int S  = 2048;   // sequence length
constexpr int B  = 2;      // batch
constexpr int H  = 16;     // heads
constexpr int DH = 64;     // head dim
constexpr int M  = B * S;  // 4096 rows

// Scratch (device globals; no allocations allowed). 16B-aligned for cp.async.
__device__ __align__(256) __half g_x[M * D];
__device__ __align__(256) __half g_y[M * D];
__device__ __align__(256) __half g_wq[D * D];
__device__ __align__(256) __half g_wk[D * D];
__device__ __align__(256) __half g_wv[D * D];
__device__ __align__(256) __half g_wo[D * D];
__device__ __align__(256) __half g_q[M * D];     // head-split [B,H,S,DH]
__device__ __align__(256) __half g_k[M * D];
__device__ __align__(256) __half g_v[M * D];
__device__ __align__(256) __half g_att[M * D];   // [B,S,H*DH]

// ---------------------------------------------------------------------------
// helpers
// ---------------------------------------------------------------------------
__device__ __forceinline__ void cp16(const void* smem_dst, const void* gmem_src) {
    unsigned d = (unsigned)__cvta_generic_to_shared(smem_dst);
    asm volatile("cp.async.cg.shared.global [%0], [%1], 16;" :: "r"(d), "l"(gmem_src));
}
__device__ __forceinline__ void cp_commit() { asm volatile("cp.async.commit_group;"); }
__device__ __forceinline__ void cp_wait0()  { asm volatile("cp.async.wait_group 0;"); }
__device__ __forceinline__ void cp_wait1()  { asm volatile("cp.async.wait_group 1;"); }

__device__ __forceinline__ uint32_t smem_u32(const void* p) {
    return (uint32_t)__cvta_generic_to_shared(p);
}

// D = A*B + D   (m16n8k16, f16 inputs, f32 accum)
__device__ __forceinline__ void mma16(float c[4],
                                      unsigned a0, unsigned a1, unsigned a2, unsigned a3,
                                      unsigned b0, unsigned b1) {
    asm volatile(
        "mma.sync.aligned.m16n8k16.row.col.f32.f16.f16.f32 "
        "{%0,%1,%2,%3},{%4,%5,%6,%7},{%8,%9},{%0,%1,%2,%3};"
        : "+f"(c[0]), "+f"(c[1]), "+f"(c[2]), "+f"(c[3])
        : "r"(a0), "r"(a1), "r"(a2), "r"(a3), "r"(b0), "r"(b1));
}

// ---------------------------------------------------------------------------
// Merged elementwise fp16 conversion: z selects which tensor.
// ---------------------------------------------------------------------------
__global__ void cvt_all(const float4* __restrict__ x,  const float4* __restrict__ y,
                        const float4* __restrict__ wq, const float4* __restrict__ wk,
                        const float4* __restrict__ wv, const float4* __restrict__ wo)
{
    const float4* src; uint2* dst; int n4;
    switch (blockIdx.z) {
        case 0: src = x;  dst = (uint2*)g_x;  n4 = M * D / 4; break;
        case 1: src = y;  dst = (uint2*)g_y;  n4 = M * D / 4; break;
        case 2: src = wq; dst = (uint2*)g_wq; n4 = D * D / 4; break;
        case 3: src = wk; dst = (uint2*)g_wk; n4 = D * D / 4; break;
        case 4: src = wv; dst = (uint2*)g_wv; n4 = D * D / 4; break;
        default: src = wo; dst = (uint2*)g_wo; n4 = D * D / 4; break;
    }
    for (int i = blockIdx.x * blockDim.x + threadIdx.x; i < n4;
         i += gridDim.x * blockDim.x) {
        float4 v = src[i];
        __half2 h01 = __floats2half2_rn(v.x, v.y);
        __half2 h23 = __floats2half2_rn(v.z, v.w);
        uint2 u;
        u.x = *reinterpret_cast<unsigned*>(&h01);
        u.y = *reinterpret_cast<unsigned*>(&h23);
        dst[i] = u;
    }
}

// ---------------------------------------------------------------------------
// GEMM: C = A[.,1024] @ W[1024,1024]^T, fp16 mma, cp.async 2-stage pipeline.
// Block 128x128, BK=64 halfs, 256 thr, 8 warps (4m x 2n), warp tile 32x64.
// mode 0: row-major fp32 out. mode 1: head-split fp16 out.
// ---------------------------------------------------------------------------
constexpr int GSTRIDE = 72;                   // halfs per smem row (64 + 8 pad)
constexpr int GT = 128 * GSTRIDE;             // halfs per (matrix,stage)
constexpr int GEMM_SMEM = 4 * GT * 2;         // 73728 B

__device__ __forceinline__
void gemm_body(const __half* __restrict__ A, const __half* __restrict__ W,
               void* __restrict__ Cout, int mode, int bx, int by)
{
    extern __shared__ __half smh[];
    const int tid    = threadIdx.x;
    const int lane   = tid & 31;
    const int warp   = tid >> 5;
    const int warp_m = warp >> 1;    // 0..3
    const int warp_n = warp & 1;     // 0..1
    const int m0 = by * 128;
    const int n0 = bx * 128;
    const int lr = lane >> 2;        // 0..7
    const int lc = lane & 3;         // 0..3

    float acc[2][8][4];
#pragma unroll
    for (int i = 0; i < 2; i++)
#pragma unroll
        for (int j = 0; j < 8; j++)
#pragma unroll
            for (int t = 0; t < 4; t++) acc[i][j][t] = 0.f;

    auto load_stage = [&](int kc, __half* As, __half* Ws) {
        const __half* Ap = A + (size_t)m0 * D + kc * 64;
        const __half* Wp = W + (size_t)n0 * D + kc * 64;
#pragma unroll
        for (int t = 0; t < 4; t++) {
            int idx = tid + 256 * t;     // 0..1023
            int row = idx >> 3;
            int seg = idx & 7;           // 8 halfs = 16B
            cp16(As + row * GSTRIDE + seg * 8, Ap + (size_t)row * D + seg * 8);
        }
#pragma unroll
        for (int t = 0; t < 4; t++) {
            int idx = tid + 256 * t;
            int row = idx >> 3;
            int seg = idx & 7;
            cp16(Ws + row * GSTRIDE + seg * 8, Wp + (size_t)row * D + seg * 8);
        }
    };

    load_stage(0, smh, smh + 2 * GT);
    cp_commit();

    for (int kt = 0; kt < 16; kt++) {
        const int s = kt & 1;
        if (kt < 15) {
            load_stage(kt + 1, smh + (s ^ 1) * GT, smh + 2 * GT + (s ^ 1) * GT);
            cp_commit();
            cp_wait1();
        } else {
            cp_wait0();
        }
        __syncthreads();

        const __half* As = smh + s * GT;
        const __half* Ws = smh + 2 * GT + s * GT;

#pragma unroll
        for (int ks = 0; ks < 4; ks++) {
            const int kc = ks * 16 + 2 * lc;
            unsigned a[2][4];
#pragma unroll
            for (int mt = 0; mt < 2; mt++) {
                int r = warp_m * 32 + mt * 16 + lr;
                a[mt][0] = *(const unsigned*)&As[r * GSTRIDE + kc];
                a[mt][1] = *(const unsigned*)&As[(r + 8) * GSTRIDE + kc];
                a[mt][2] = *(const unsigned*)&As[r * GSTRIDE + kc + 8];
                a[mt][3] = *(const unsigned*)&As[(r + 8) * GSTRIDE + kc + 8];
            }
#pragma unroll
            for (int nt = 0; nt < 8; nt++) {
                int n = warp_n * 64 + nt * 8 + lr;
                unsigned b0 = *(const unsigned*)&Ws[n * GSTRIDE + kc];
                unsigned b1 = *(const unsigned*)&Ws[n * GSTRIDE + kc + 8];
#pragma unroll
                for (int mt = 0; mt < 2; mt++)
                    mma16(acc[mt][nt], a[mt][0], a[mt][1], a[mt][2], a[mt][3], b0, b1);
            }
        }
        __syncthreads();
    }

#pragma unroll
    for (int mt = 0; mt < 2; mt++) {
#pragma unroll
        for (int nt = 0; nt < 8; nt++) {
            int rA = m0 + warp_m * 32 + mt * 16 + lr;
            int cA = n0 + warp_n * 64 + nt * 8 + 2 * lc;
#pragma unroll
            for (int half_i = 0; half_i < 2; half_i++) {
                int m = rA + half_i * 8;
                float v0 = acc[mt][nt][half_i * 2 + 0];
                float v1 = acc[mt][nt][half_i * 2 + 1];
                if (mode == 0) {
                    *(float2*)((float*)Cout + (size_t)m * D + cA) = make_float2(v0, v1);
                } else {
                    int bb = m >> 11;
                    int ss = m & (S - 1);
                    int hh = cA >> 6;
                    int dh = cA & (DH - 1);
                    __half* dst = (__half*)Cout + (((size_t)(bb * H + hh) * S + ss) * DH + dh);
                    *(__half2*)dst = __floats2half2_rn(v0, v1);
                }
            }
        }
    }
}

__global__ __launch_bounds__(256, 2)
void qkv_gemm()
{
    const __half* A; const __half* W; __half* C;
    if (blockIdx.z == 0)      { A = g_y; W = g_wq; C = g_q; }
    else if (blockIdx.z == 1) { A = g_x; W = g_wk; C = g_k; }
    else                      { A = g_x; W = g_wv; C = g_v; }
    gemm_body(A, W, C, 1, blockIdx.x, blockIdx.y);
}

__global__ __launch_bounds__(256, 2)
void o_gemm(float* __restrict__ Out)
{
    gemm_body(g_att, g_wo, Out, 0, blockIdx.x, blockIdx.y);
}

// ---------------------------------------------------------------------------
// Flash attention, naive softmax, fp16 mma, cp.async double-buffered K/V.
// CTA = 128 q-rows of one (b,h), 256 thr / 8 warps (16 rows each), k-tile 64.
// smem (halfs): K 2x64x72, V 2x64x72, P 128x72 (Q staged through P once).
// PV B-fragments loaded via ldmatrix.x4.trans from V[k][d].
// ---------------------------------------------------------------------------
constexpr int KST = 64 * 72;     // halfs per K/V stage
constexpr int PST = 128 * 72;
constexpr int ATTN_SMEM = (4 * KST + PST) * 2;   // 55296 B

__global__ __launch_bounds__(256, 2)
void flash_attn(const float* __restrict__ mask)
{
    extern __shared__ __half smh[];
    __half* Ks2 = smh;               // 2 stages of 64x72
    __half* Vs2 = smh + 2 * KST;     // 2 stages of 64x72
    __half* Ps  = smh + 4 * KST;     // 128 x 72 (Q staging, then P)

    const int tid  = threadIdx.x;
    const int lane = tid & 31;
    const int warp = tid >> 5;
    const int lr = lane >> 2;      // 0..7
    const int lc = lane & 3;       // 0..3
    const int bh = blockIdx.y;
    const int qb = blockIdx.x * 128;

    const __half* qp    = g_q + ((size_t)bh * S + qb) * DH;
    const __half* kbase = g_k + (size_t)bh * S * DH;
    const __half* vbase = g_v + (size_t)bh * S * DH;

    auto kv_load = [&](int kb, __half* Kd, __half* Vd) {
#pragma unroll
        for (int t = 0; t < 2; t++) {
            int idx = tid + 256 * t;   // 0..511
            int row = idx >> 3;        // 0..63
            int seg = idx & 7;
            cp16(Kd + row * 72 + seg * 8, kbase + (size_t)(kb + row) * DH + seg * 8);
        }
#pragma unroll
        for (int t = 0; t < 2; t++) {
            int idx = tid + 256 * t;
            int row = idx >> 3;
            int seg = idx & 7;
            cp16(Vd + row * 72 + seg * 8, vbase + (size_t)(kb + row) * DH + seg * 8);
        }
    };

    // Stage Q (128 x 64 halfs) into Ps
#pragma unroll
    for (int t = 0; t < 4; t++) {
        int idx = tid + 256 * t;       // 0..1023
        int row = idx >> 3;            // 0..127
        int seg = idx & 7;
        cp16(&Ps[row * 72 + seg * 8], qp + (size_t)row * DH + seg * 8);
    }
    cp_commit();
    kv_load(0, Ks2, Vs2);
    cp_commit();
    cp_wait1();          // Q complete (KV0 may still be in flight)
    __syncthreads();

    const int r0 = warp * 16 + lr;       // warp-local q row (of 128)

    // Q fragments in registers for the whole loop (DH=64 -> 4 k16 steps)
    unsigned qf[4][4];
#pragma unroll
    for (int ks = 0; ks < 4; ks++) {
        const int kc = ks * 16 + 2 * lc;
        qf[ks][0] = *(const unsigned*)&Ps[r0 * 72 + kc];
        qf[ks][1] = *(const unsigned*)&Ps[(r0 + 8) * 72 + kc];
        qf[ks][2] = *(const unsigned*)&Ps[r0 * 72 + kc + 8];
        qf[ks][3] = *(const unsigned*)&Ps[(r0 + 8) * 72 + kc + 8];
    }

    float accO[8][4];
#pragma unroll
    for (int i = 0; i < 8; i++)
#pragma unroll
        for (int t = 0; t < 4; t++) accO[i][t] = 0.f;
    float rs0 = 0.f, rs1 = 0.f;

    for (int kt = 0; kt < S / 64; kt++) {
        const int s = kt & 1;
        if (kt < S / 64 - 1) {
            kv_load((kt + 1) * 64, Ks2 + (s ^ 1) * KST, Vs2 + (s ^ 1) * KST);
            cp_commit();
            cp_wait1();     // KV[kt] done, KV[kt+1] in flight
        } else {
            cp_wait0();
        }
        __syncthreads();    // KV[kt] visible; prior-stage reads done

        const __half* Ks = Ks2 + s * KST;
        const __half* Vs = Vs2 + s * KST;
        const int kb = kt * 64;

        // S = Q K^T  (warp: 16 x 64)
        float sAcc[8][4];
#pragma unroll
        for (int i = 0; i < 8; i++)
#pragma unroll
            for (int t = 0; t < 4; t++) sAcc[i][t] = 0.f;
#pragma unroll
        for (int ks = 0; ks < 4; ks++) {
            const int kc = ks * 16 + 2 * lc;
#pragma unroll
            for (int nt = 0; nt < 8; nt++) {
                int n = nt * 8 + lr;
                unsigned b0 = *(const unsigned*)&Ks[n * 72 + kc];
                unsigned b1 = *(const unsigned*)&Ks[n * 72 + kc + 8];
                mma16(sAcc[nt], qf[ks][0], qf[ks][1], qf[ks][2], qf[ks][3], b0, b1);
            }
        }

        // exp(scale + mask), accumulate row sums, write P (fp16) to smem
#pragma unroll
        for (int nt = 0; nt < 8; nt++) {
            int col = nt * 8 + 2 * lc;
            float2 m0v = *(const float2*)(mask + (size_t)(qb + r0) * S + kb + col);
            float2 m1v = *(const float2*)(mask + (size_t)(qb + r0 + 8) * S + kb + col);
            float e00 = __expf(fmaf(sAcc[nt][0], 0.125f, m0v.x));
            float e01 = __expf(fmaf(sAcc[nt][1], 0.125f, m0v.y));
            float e10 = __expf(fmaf(sAcc[nt][2], 0.125f, m1v.x));
            float e11 = __expf(fmaf(sAcc[nt][3], 0.125f, m1v.y));
            rs0 += e00 + e01;
            rs1 += e10 + e11;
            *(__half2*)&Ps[r0 * 72 + col]       = __floats2half2_rn(e00, e01);
            *(__half2*)&Ps[(r0 + 8) * 72 + col] = __floats2half2_rn(e10, e11);
        }
        __syncwarp();

        // O += P V   (P: warp's 16 x 64 from Ps; V frags via ldmatrix.trans)
#pragma unroll
        for (int ktc = 0; ktc < 4; ktc++) {
            const int kc = ktc * 16 + 2 * lc;
            unsigned a0 = *(const unsigned*)&Ps[r0 * 72 + kc];
            unsigned a1 = *(const unsigned*)&Ps[(r0 + 8) * 72 + kc];
            unsigned a2 = *(const unsigned*)&Ps[r0 * 72 + kc + 8];
            unsigned a3 = *(const unsigned*)&Ps[(r0 + 8) * 72 + kc + 8];
#pragma unroll
            for (int dtp = 0; dtp < 4; dtp++) {
                const int grp = lane >> 3;
                const int ii  = lane & 7;
                const int vrow = ktc * 16 + ((grp & 1) << 3) + ii;
                const int vcol = (dtp * 2 + (grp >> 1)) * 8;
                uint32_t addr = smem_u32(&Vs[vrow * 72 + vcol]);
                unsigned v0, v1, v2, v3;
                asm volatile(
                    "ldmatrix.sync.aligned.m8n8.x4.trans.shared.b16 {%0,%1,%2,%3}, [%4];"
                    : "=r"(v0), "=r"(v1), "=r"(v2), "=r"(v3) : "r"(addr));
                mma16(accO[dtp * 2],     a0, a1, a2, a3, v0, v1);
                mma16(accO[dtp * 2 + 1], a0, a1, a2, a3, v2, v3);
            }
        }
        __syncthreads();    // stage-s reads done before next prefetch overwrites
    }

    // full row sums (cols of a row live in the 4 lanes of a quad)
    rs0 += __shfl_xor_sync(0xffffffffu, rs0, 1);
    rs0 += __shfl_xor_sync(0xffffffffu, rs0, 2);
    rs1 += __shfl_xor_sync(0xffffffffu, rs1, 1);
    rs1 += __shfl_xor_sync(0xffffffffu, rs1, 2);
    float inv0 = 1.f / (rs0 + 1e-10f);
    float inv1 = 1.f / (rs1 + 1e-10f);

    const int bb = bh >> 4;        // bh / H
    const int hh = bh & (H - 1);
    const int mrow0 = qb + r0;
#pragma unroll
    for (int dt = 0; dt < 8; dt++) {
        int col = hh * DH + dt * 8 + 2 * lc;
        __half* dst0 = g_att + ((size_t)(bb * S + mrow0)) * D + col;
        __half* dst1 = g_att + ((size_t)(bb * S + mrow0 + 8)) * D + col;
        *(__half2*)dst0 = __floats2half2_rn(accO[dt][0] * inv0, accO[dt][1] * inv0);
        *(__half2*)dst1 = __floats2half2_rn(accO[dt][2] * inv1, accO[dt][3] * inv1);
    }
}

// ---------------------------------------------------------------------------
extern "C" void kernel_launch(void* const* d_in, const int* in_sizes, int n_in,
                              void* d_out, int out_size)
{
    (void)in_sizes; (void)n_in; (void)out_size;
    const float* x    = (const float*)d_in[0];
    const float* y    = (const float*)d_in[1];
    const float* mask = (const float*)d_in[2];
    const float* Wq   = (const float*)d_in[3];
    const float* Wk   = (const float*)d_in[4];
    const float* Wv   = (const float*)d_in[5];
    const float* Wo   = (const float*)d_in[6];
    float* out = (float*)d_out;

    static bool attr_set = false;
    if (!attr_set) {
        cudaFuncSetAttribute(flash_attn, cudaFuncAttributeMaxDynamicSharedMemorySize,
                             ATTN_SMEM);
        cudaFuncSetAttribute(qkv_gemm, cudaFuncAttributeMaxDynamicSharedMemorySize,
                             GEMM_SMEM);
        cudaFuncSetAttribute(o_gemm, cudaFuncAttributeMaxDynamicSharedMemorySize,
                             GEMM_SMEM);
        attr_set = true;
    }

    cvt_all<<<dim3(512, 1, 6), 256>>>((const float4*)x,  (const float4*)y,
                                      (const float4*)Wq, (const float4*)Wk,
                                      (const float4*)Wv, (const float4*)Wo);

    qkv_gemm<<<dim3(D / 128, M / 128, 3), 256, GEMM_SMEM>>>();
    flash_attn<<<dim3(S / 128, B * H), 256, ATTN_SMEM>>>(mask);
    o_gemm<<<dim3(D / 128, M / 128), 256, GEMM_SMEM>>>(out);
}

// round 10
// speedup vs baseline: 11.0380x; 1.1488x over previous
#include <cuda_runtime.h>
#include <cuda_fp16.h>
#include <cstdint>

// Problem constants
constexpr int D  = 1024;   // d_model
constexpr int S  = 2048;   // sequence length
constexpr int B  = 2;      // batch
constexpr int H  = 16;     // heads
constexpr int DH = 64;     // head dim
constexpr int M  = B * S;  // 4096 rows

// Scratch (device globals; no allocations allowed). 16B-aligned for cp.async.
__device__ __align__(256) __half g_x[M * D];
__device__ __align__(256) __half g_y[M * D];
__device__ __align__(256) __half g_wq[D * D];
__device__ __align__(256) __half g_wk[D * D];
__device__ __align__(256) __half g_wv[D * D];
__device__ __align__(256) __half g_wo[D * D];
__device__ __align__(256) __half g_q[M * D];     // head-split [B,H,S,DH]
__device__ __align__(256) __half g_k[M * D];
__device__ __align__(256) __half g_v[M * D];
__device__ __align__(256) __half g_att[M * D];   // [B,S,H*DH]
__device__ int g_mask_nz;                         // 1 if mask has any nonzero

// ---------------------------------------------------------------------------
// helpers
// ---------------------------------------------------------------------------
__device__ __forceinline__ void cp16(const void* smem_dst, const void* gmem_src) {
    unsigned d = (unsigned)__cvta_generic_to_shared(smem_dst);
    asm volatile("cp.async.cg.shared.global [%0], [%1], 16;" :: "r"(d), "l"(gmem_src));
}
__device__ __forceinline__ void cp_commit() { asm volatile("cp.async.commit_group;"); }
__device__ __forceinline__ void cp_wait0()  { asm volatile("cp.async.wait_group 0;"); }
__device__ __forceinline__ void cp_wait1()  { asm volatile("cp.async.wait_group 1;"); }

__device__ __forceinline__ uint32_t smem_u32(const void* p) {
    return (uint32_t)__cvta_generic_to_shared(p);
}

// D = A*B + D   (m16n8k16, f16 inputs, f32 accum)
__device__ __forceinline__ void mma16(float c[4],
                                      unsigned a0, unsigned a1, unsigned a2, unsigned a3,
                                      unsigned b0, unsigned b1) {
    asm volatile(
        "mma.sync.aligned.m16n8k16.row.col.f32.f16.f16.f32 "
        "{%0,%1,%2,%3},{%4,%5,%6,%7},{%8,%9},{%0,%1,%2,%3};"
        : "+f"(c[0]), "+f"(c[1]), "+f"(c[2]), "+f"(c[3])
        : "r"(a0), "r"(a1), "r"(a2), "r"(a3), "r"(b0), "r"(b1));
}

// ---------------------------------------------------------------------------
// Mask zero detection: reset flag, then OR-reduce nonzero-ness.
// ---------------------------------------------------------------------------
__global__ void mask_reset() { g_mask_nz = 0; }

__global__ void mask_check(const float4* __restrict__ m, int n4)
{
    int found = 0;
    for (int i = blockIdx.x * blockDim.x + threadIdx.x; i < n4;
         i += gridDim.x * blockDim.x) {
        float4 v = m[i];
        if (v.x != 0.f || v.y != 0.f || v.z != 0.f || v.w != 0.f) { found = 1; break; }
    }
    if (__syncthreads_or(found)) {
        if (threadIdx.x == 0) atomicOr(&g_mask_nz, 1);
    }
}

// ---------------------------------------------------------------------------
// Merged elementwise fp16 conversion: z selects which tensor.
// ---------------------------------------------------------------------------
__global__ void cvt_all(const float4* __restrict__ x,  const float4* __restrict__ y,
                        const float4* __restrict__ wq, const float4* __restrict__ wk,
                        const float4* __restrict__ wv, const float4* __restrict__ wo)
{
    const float4* src; uint2* dst; int n4;
    switch (blockIdx.z) {
        case 0: src = x;  dst = (uint2*)g_x;  n4 = M * D / 4; break;
        case 1: src = y;  dst = (uint2*)g_y;  n4 = M * D / 4; break;
        case 2: src = wq; dst = (uint2*)g_wq; n4 = D * D / 4; break;
        case 3: src = wk; dst = (uint2*)g_wk; n4 = D * D / 4; break;
        case 4: src = wv; dst = (uint2*)g_wv; n4 = D * D / 4; break;
        default: src = wo; dst = (uint2*)g_wo; n4 = D * D / 4; break;
    }
    for (int i = blockIdx.x * blockDim.x + threadIdx.x; i < n4;
         i += gridDim.x * blockDim.x) {
        float4 v = src[i];
        __half2 h01 = __floats2half2_rn(v.x, v.y);
        __half2 h23 = __floats2half2_rn(v.z, v.w);
        uint2 u;
        u.x = *reinterpret_cast<unsigned*>(&h01);
        u.y = *reinterpret_cast<unsigned*>(&h23);
        dst[i] = u;
    }
}

// ---------------------------------------------------------------------------
// GEMM: C = A[.,1024] @ W[1024,1024]^T, fp16 mma, cp.async 2-stage pipeline.
// Block 128x128, BK=64 halfs, 256 thr, 8 warps (4m x 2n), warp tile 32x64.
// mode 0: row-major fp32 out. mode 1: head-split fp16 out.
// ---------------------------------------------------------------------------
constexpr int GSTRIDE = 72;                   // halfs per smem row (64 + 8 pad)
constexpr int GT = 128 * GSTRIDE;             // halfs per (matrix,stage)
constexpr int GEMM_SMEM = 4 * GT * 2;         // 73728 B

__device__ __forceinline__
void gemm_body(const __half* __restrict__ A, const __half* __restrict__ W,
               void* __restrict__ Cout, int mode, int bx, int by)
{
    extern __shared__ __half smh[];
    const int tid    = threadIdx.x;
    const int lane   = tid & 31;
    const int warp   = tid >> 5;
    const int warp_m = warp >> 1;    // 0..3
    const int warp_n = warp & 1;     // 0..1
    const int m0 = by * 128;
    const int n0 = bx * 128;
    const int lr = lane >> 2;        // 0..7
    const int lc = lane & 3;         // 0..3

    float acc[2][8][4];
#pragma unroll
    for (int i = 0; i < 2; i++)
#pragma unroll
        for (int j = 0; j < 8; j++)
#pragma unroll
            for (int t = 0; t < 4; t++) acc[i][j][t] = 0.f;

    auto load_stage = [&](int kc, __half* As, __half* Ws) {
        const __half* Ap = A + (size_t)m0 * D + kc * 64;
        const __half* Wp = W + (size_t)n0 * D + kc * 64;
#pragma unroll
        for (int t = 0; t < 4; t++) {
            int idx = tid + 256 * t;     // 0..1023
            int row = idx >> 3;
            int seg = idx & 7;           // 8 halfs = 16B
            cp16(As + row * GSTRIDE + seg * 8, Ap + (size_t)row * D + seg * 8);
        }
#pragma unroll
        for (int t = 0; t < 4; t++) {
            int idx = tid + 256 * t;
            int row = idx >> 3;
            int seg = idx & 7;
            cp16(Ws + row * GSTRIDE + seg * 8, Wp + (size_t)row * D + seg * 8);
        }
    };

    load_stage(0, smh, smh + 2 * GT);
    cp_commit();

    for (int kt = 0; kt < 16; kt++) {
        const int s = kt & 1;
        if (kt < 15) {
            load_stage(kt + 1, smh + (s ^ 1) * GT, smh + 2 * GT + (s ^ 1) * GT);
            cp_commit();
            cp_wait1();
        } else {
            cp_wait0();
        }
        __syncthreads();

        const __half* As = smh + s * GT;
        const __half* Ws = smh + 2 * GT + s * GT;

#pragma unroll
        for (int ks = 0; ks < 4; ks++) {
            const int kc = ks * 16 + 2 * lc;
            unsigned a[2][4];
#pragma unroll
            for (int mt = 0; mt < 2; mt++) {
                int r = warp_m * 32 + mt * 16 + lr;
                a[mt][0] = *(const unsigned*)&As[r * GSTRIDE + kc];
                a[mt][1] = *(const unsigned*)&As[(r + 8) * GSTRIDE + kc];
                a[mt][2] = *(const unsigned*)&As[r * GSTRIDE + kc + 8];
                a[mt][3] = *(const unsigned*)&As[(r + 8) * GSTRIDE + kc + 8];
            }
#pragma unroll
            for (int nt = 0; nt < 8; nt++) {
                int n = warp_n * 64 + nt * 8 + lr;
                unsigned b0 = *(const unsigned*)&Ws[n * GSTRIDE + kc];
                unsigned b1 = *(const unsigned*)&Ws[n * GSTRIDE + kc + 8];
#pragma unroll
                for (int mt = 0; mt < 2; mt++)
                    mma16(acc[mt][nt], a[mt][0], a[mt][1], a[mt][2], a[mt][3], b0, b1);
            }
        }
        __syncthreads();
    }

#pragma unroll
    for (int mt = 0; mt < 2; mt++) {
#pragma unroll
        for (int nt = 0; nt < 8; nt++) {
            int rA = m0 + warp_m * 32 + mt * 16 + lr;
            int cA = n0 + warp_n * 64 + nt * 8 + 2 * lc;
#pragma unroll
            for (int half_i = 0; half_i < 2; half_i++) {
                int m = rA + half_i * 8;
                float v0 = acc[mt][nt][half_i * 2 + 0];
                float v1 = acc[mt][nt][half_i * 2 + 1];
                if (mode == 0) {
                    *(float2*)((float*)Cout + (size_t)m * D + cA) = make_float2(v0, v1);
                } else {
                    int bb = m >> 11;
                    int ss = m & (S - 1);
                    int hh = cA >> 6;
                    int dh = cA & (DH - 1);
                    __half* dst = (__half*)Cout + (((size_t)(bb * H + hh) * S + ss) * DH + dh);
                    *(__half2*)dst = __floats2half2_rn(v0, v1);
                }
            }
        }
    }
}

__global__ __launch_bounds__(256, 2)
void qkv_gemm()
{
    const __half* A; const __half* W; __half* C;
    if (blockIdx.z == 0)      { A = g_y; W = g_wq; C = g_q; }
    else if (blockIdx.z == 1) { A = g_x; W = g_wk; C = g_k; }
    else                      { A = g_x; W = g_wv; C = g_v; }
    gemm_body(A, W, C, 1, blockIdx.x, blockIdx.y);
}

__global__ __launch_bounds__(256, 2)
void o_gemm(float* __restrict__ Out)
{
    gemm_body(g_att, g_wo, Out, 0, blockIdx.x, blockIdx.y);
}

// ---------------------------------------------------------------------------
// Flash attention, naive softmax, fp16 mma, cp.async double-buffered K/V.
// CTA = 128 q-rows of one (b,h), 256 thr / 8 warps (16 rows each), k-tile 64.
// smem (halfs): K 2x64x72, V 2x64x72, P 128x72 (Q staged through P once).
// PV B-fragments loaded via ldmatrix.x4.trans from V[k][d].
// Mask loads skipped entirely when g_mask_nz == 0 (detected per-call).
// ---------------------------------------------------------------------------
constexpr int KST = 64 * 72;     // halfs per K/V stage
constexpr int PST = 128 * 72;
constexpr int ATTN_SMEM = (4 * KST + PST) * 2;   // 55296 B

__global__ __launch_bounds__(256, 2)
void flash_attn(const float* __restrict__ mask)
{
    extern __shared__ __half smh[];
    __half* Ks2 = smh;               // 2 stages of 64x72
    __half* Vs2 = smh + 2 * KST;     // 2 stages of 64x72
    __half* Ps  = smh + 4 * KST;     // 128 x 72 (Q staging, then P)

    const int tid  = threadIdx.x;
    const int lane = tid & 31;
    const int warp = tid >> 5;
    const int lr = lane >> 2;      // 0..7
    const int lc = lane & 3;       // 0..3
    const int bh = blockIdx.y;
    const int qb = blockIdx.x * 128;
    const int mnz = g_mask_nz;     // uniform per launch

    const __half* qp    = g_q + ((size_t)bh * S + qb) * DH;
    const __half* kbase = g_k + (size_t)bh * S * DH;
    const __half* vbase = g_v + (size_t)bh * S * DH;

    auto kv_load = [&](int kb, __half* Kd, __half* Vd) {
#pragma unroll
        for (int t = 0; t < 2; t++) {
            int idx = tid + 256 * t;   // 0..511
            int row = idx >> 3;        // 0..63
            int seg = idx & 7;
            cp16(Kd + row * 72 + seg * 8, kbase + (size_t)(kb + row) * DH + seg * 8);
        }
#pragma unroll
        for (int t = 0; t < 2; t++) {
            int idx = tid + 256 * t;
            int row = idx >> 3;
            int seg = idx & 7;
            cp16(Vd + row * 72 + seg * 8, vbase + (size_t)(kb + row) * DH + seg * 8);
        }
    };

    // Stage Q (128 x 64 halfs) into Ps
#pragma unroll
    for (int t = 0; t < 4; t++) {
        int idx = tid + 256 * t;       // 0..1023
        int row = idx >> 3;            // 0..127
        int seg = idx & 7;
        cp16(&Ps[row * 72 + seg * 8], qp + (size_t)row * DH + seg * 8);
    }
    cp_commit();
    kv_load(0, Ks2, Vs2);
    cp_commit();
    cp_wait1();          // Q complete (KV0 may still be in flight)
    __syncthreads();

    const int r0 = warp * 16 + lr;       // warp-local q row (of 128)

    // Q fragments in registers for the whole loop (DH=64 -> 4 k16 steps)
    unsigned qf[4][4];
#pragma unroll
    for (int ks = 0; ks < 4; ks++) {
        const int kc = ks * 16 + 2 * lc;
        qf[ks][0] = *(const unsigned*)&Ps[r0 * 72 + kc];
        qf[ks][1] = *(const unsigned*)&Ps[(r0 + 8) * 72 + kc];
        qf[ks][2] = *(const unsigned*)&Ps[r0 * 72 + kc + 8];
        qf[ks][3] = *(const unsigned*)&Ps[(r0 + 8) * 72 + kc + 8];
    }

    float accO[8][4];
#pragma unroll
    for (int i = 0; i < 8; i++)
#pragma unroll
        for (int t = 0; t < 4; t++) accO[i][t] = 0.f;
    float rs0 = 0.f, rs1 = 0.f;

    for (int kt = 0; kt < S / 64; kt++) {
        const int s = kt & 1;
        if (kt < S / 64 - 1) {
            kv_load((kt + 1) * 64, Ks2 + (s ^ 1) * KST, Vs2 + (s ^ 1) * KST);
            cp_commit();
            cp_wait1();     // KV[kt] done, KV[kt+1] in flight
        } else {
            cp_wait0();
        }
        __syncthreads();    // KV[kt] visible; prior-stage reads done

        const __half* Ks = Ks2 + s * KST;
        const __half* Vs = Vs2 + s * KST;
        const int kb = kt * 64;

        // S = Q K^T  (warp: 16 x 64)
        float sAcc[8][4];
#pragma unroll
        for (int i = 0; i < 8; i++)
#pragma unroll
            for (int t = 0; t < 4; t++) sAcc[i][t] = 0.f;
#pragma unroll
        for (int ks = 0; ks < 4; ks++) {
            const int kc = ks * 16 + 2 * lc;
#pragma unroll
            for (int nt = 0; nt < 8; nt++) {
                int n = nt * 8 + lr;
                unsigned b0 = *(const unsigned*)&Ks[n * 72 + kc];
                unsigned b1 = *(const unsigned*)&Ks[n * 72 + kc + 8];
                mma16(sAcc[nt], qf[ks][0], qf[ks][1], qf[ks][2], qf[ks][3], b0, b1);
            }
        }

        // exp(scale + mask), accumulate row sums, write P (fp16) to smem.
        // Mask loads skipped when mask is all-zero (math identical: fmaf with 0).
#pragma unroll
        for (int nt = 0; nt < 8; nt++) {
            int col = nt * 8 + 2 * lc;
            float2 m0v = make_float2(0.f, 0.f);
            float2 m1v = make_float2(0.f, 0.f);
            if (mnz) {
                m0v = *(const float2*)(mask + (size_t)(qb + r0) * S + kb + col);
                m1v = *(const float2*)(mask + (size_t)(qb + r0 + 8) * S + kb + col);
            }
            float e00 = __expf(fmaf(sAcc[nt][0], 0.125f, m0v.x));
            float e01 = __expf(fmaf(sAcc[nt][1], 0.125f, m0v.y));
            float e10 = __expf(fmaf(sAcc[nt][2], 0.125f, m1v.x));
            float e11 = __expf(fmaf(sAcc[nt][3], 0.125f, m1v.y));
            rs0 += e00 + e01;
            rs1 += e10 + e11;
            *(__half2*)&Ps[r0 * 72 + col]       = __floats2half2_rn(e00, e01);
            *(__half2*)&Ps[(r0 + 8) * 72 + col] = __floats2half2_rn(e10, e11);
        }
        __syncwarp();

        // O += P V   (P: warp's 16 x 64 from Ps; V frags via ldmatrix.trans)
#pragma unroll
        for (int ktc = 0; ktc < 4; ktc++) {
            const int kc = ktc * 16 + 2 * lc;
            unsigned a0 = *(const unsigned*)&Ps[r0 * 72 + kc];
            unsigned a1 = *(const unsigned*)&Ps[(r0 + 8) * 72 + kc];
            unsigned a2 = *(const unsigned*)&Ps[r0 * 72 + kc + 8];
            unsigned a3 = *(const unsigned*)&Ps[(r0 + 8) * 72 + kc + 8];
#pragma unroll
            for (int dtp = 0; dtp < 4; dtp++) {
                const int grp = lane >> 3;
                const int ii  = lane & 7;
                const int vrow = ktc * 16 + ((grp & 1) << 3) + ii;
                const int vcol = (dtp * 2 + (grp >> 1)) * 8;
                uint32_t addr = smem_u32(&Vs[vrow * 72 + vcol]);
                unsigned v0, v1, v2, v3;
                asm volatile(
                    "ldmatrix.sync.aligned.m8n8.x4.trans.shared.b16 {%0,%1,%2,%3}, [%4];"
                    : "=r"(v0), "=r"(v1), "=r"(v2), "=r"(v3) : "r"(addr));
                mma16(accO[dtp * 2],     a0, a1, a2, a3, v0, v1);
                mma16(accO[dtp * 2 + 1], a0, a1, a2, a3, v2, v3);
            }
        }
        __syncthreads();    // stage-s reads done before next prefetch overwrites
    }

    // full row sums (cols of a row live in the 4 lanes of a quad)
    rs0 += __shfl_xor_sync(0xffffffffu, rs0, 1);
    rs0 += __shfl_xor_sync(0xffffffffu, rs0, 2);
    rs1 += __shfl_xor_sync(0xffffffffu, rs1, 1);
    rs1 += __shfl_xor_sync(0xffffffffu, rs1, 2);
    float inv0 = 1.f / (rs0 + 1e-10f);
    float inv1 = 1.f / (rs1 + 1e-10f);

    const int bb = bh >> 4;        // bh / H
    const int hh = bh & (H - 1);
    const int mrow0 = qb + r0;
#pragma unroll
    for (int dt = 0; dt < 8; dt++) {
        int col = hh * DH + dt * 8 + 2 * lc;
        __half* dst0 = g_att + ((size_t)(bb * S + mrow0)) * D + col;
        __half* dst1 = g_att + ((size_t)(bb * S + mrow0 + 8)) * D + col;
        *(__half2*)dst0 = __floats2half2_rn(accO[dt][0] * inv0, accO[dt][1] * inv0);
        *(__half2*)dst1 = __floats2half2_rn(accO[dt][2] * inv1, accO[dt][3] * inv1);
    }
}

// ---------------------------------------------------------------------------
extern "C" void kernel_launch(void* const* d_in, const int* in_sizes, int n_in,
                              void* d_out, int out_size)
{
    (void)in_sizes; (void)n_in; (void)out_size;
    const float* x    = (const float*)d_in[0];
    const float* y    = (const float*)d_in[1];
    const float* mask = (const float*)d_in[2];
    const float* Wq   = (const float*)d_in[3];
    const float* Wk   = (const float*)d_in[4];
    const float* Wv   = (const float*)d_in[5];
    const float* Wo   = (const float*)d_in[6];
    float* out = (float*)d_out;

    static bool attr_set = false;
    if (!attr_set) {
        cudaFuncSetAttribute(flash_attn, cudaFuncAttributeMaxDynamicSharedMemorySize,
                             ATTN_SMEM);
        cudaFuncSetAttribute(qkv_gemm, cudaFuncAttributeMaxDynamicSharedMemorySize,
                             GEMM_SMEM);
        cudaFuncSetAttribute(o_gemm, cudaFuncAttributeMaxDynamicSharedMemorySize,
                             GEMM_SMEM);
        attr_set = true;
    }

    // mask nonzero detection (cheap OR-reduction; flash reads the flag)
    mask_reset<<<1, 1>>>();
    mask_check<<<512, 256>>>((const float4*)mask, S * S / 4);

    cvt_all<<<dim3(512, 1, 6), 256>>>((const float4*)x,  (const float4*)y,
                                      (const float4*)Wq, (const float4*)Wk,
                                      (const float4*)Wv, (const float4*)Wo);

    qkv_gemm<<<dim3(D / 128, M / 128, 3), 256, GEMM_SMEM>>>();
    flash_attn<<<dim3(S / 128, B * H), 256, ATTN_SMEM>>>(mask);
    o_gemm<<<dim3(D / 128, M / 128), 256, GEMM_SMEM>>>(out);
}

// round 11
// speedup vs baseline: 12.5622x; 1.1381x over previous
#include <cuda_runtime.h>
#include <cuda_fp16.h>
#include <cstdint>

// Problem constants
constexpr int D  = 1024;   // d_model
constexpr int S  = 2048;   // sequence length
constexpr int B  = 2;      // batch
constexpr int H  = 16;     // heads
constexpr int DH = 64;     // head dim
constexpr int M  = B * S;  // 4096 rows

// Scratch (device globals; no allocations allowed). 16B-aligned for cp.async.
__device__ __align__(256) __half g_x[M * D];
__device__ __align__(256) __half g_y[M * D];
__device__ __align__(256) __half g_wq[D * D];
__device__ __align__(256) __half g_wk[D * D];
__device__ __align__(256) __half g_wv[D * D];
__device__ __align__(256) __half g_wo[D * D];
__device__ __align__(256) __half g_q[M * D];     // head-split [B,H,S,DH]
__device__ __align__(256) __half g_k[M * D];
__device__ __align__(256) __half g_v[M * D];
__device__ __align__(256) __half g_att[M * D];   // [B,S,H*DH]
__device__ int g_mask_nz;                         // 1 if mask has any nonzero

// ---------------------------------------------------------------------------
// helpers
// ---------------------------------------------------------------------------
__device__ __forceinline__ void cp16(const void* smem_dst, const void* gmem_src) {
    unsigned d = (unsigned)__cvta_generic_to_shared(smem_dst);
    asm volatile("cp.async.cg.shared.global [%0], [%1], 16;" :: "r"(d), "l"(gmem_src));
}
__device__ __forceinline__ void cp_commit() { asm volatile("cp.async.commit_group;"); }
__device__ __forceinline__ void cp_wait0()  { asm volatile("cp.async.wait_group 0;"); }
__device__ __forceinline__ void cp_wait1()  { asm volatile("cp.async.wait_group 1;"); }

__device__ __forceinline__ uint32_t smem_u32(const void* p) {
    return (uint32_t)__cvta_generic_to_shared(p);
}

// D = A*B + D   (m16n8k16, f16 inputs, f32 accum)
__device__ __forceinline__ void mma16(float c[4],
                                      unsigned a0, unsigned a1, unsigned a2, unsigned a3,
                                      unsigned b0, unsigned b1) {
    asm volatile(
        "mma.sync.aligned.m16n8k16.row.col.f32.f16.f16.f32 "
        "{%0,%1,%2,%3},{%4,%5,%6,%7},{%8,%9},{%0,%1,%2,%3};"
        : "+f"(c[0]), "+f"(c[1]), "+f"(c[2]), "+f"(c[3])
        : "r"(a0), "r"(a1), "r"(a2), "r"(a3), "r"(b0), "r"(b1));
}

__device__ __forceinline__ void ldm_x4(unsigned r[4], uint32_t addr) {
    asm volatile("ldmatrix.sync.aligned.m8n8.x4.shared.b16 {%0,%1,%2,%3}, [%4];"
                 : "=r"(r[0]), "=r"(r[1]), "=r"(r[2]), "=r"(r[3]) : "r"(addr));
}

// ---------------------------------------------------------------------------
// Merged elementwise fp16 conversion + mask nonzero check (z = 6).
// ---------------------------------------------------------------------------
__global__ void cvt_all(const float4* __restrict__ x,  const float4* __restrict__ y,
                        const float4* __restrict__ wq, const float4* __restrict__ wk,
                        const float4* __restrict__ wv, const float4* __restrict__ wo,
                        const float4* __restrict__ mask)
{
    if (blockIdx.z == 6) {     // mask check (flag pre-cleared by memset)
        int found = 0;
        const int n4 = S * S / 4;
        for (int i = blockIdx.x * blockDim.x + threadIdx.x; i < n4;
             i += gridDim.x * blockDim.x) {
            float4 v = mask[i];
            if (v.x != 0.f || v.y != 0.f || v.z != 0.f || v.w != 0.f) { found = 1; break; }
        }
        if (__syncthreads_or(found)) {
            if (threadIdx.x == 0) atomicOr(&g_mask_nz, 1);
        }
        return;
    }
    const float4* src; uint2* dst; int n4;
    switch (blockIdx.z) {
        case 0: src = x;  dst = (uint2*)g_x;  n4 = M * D / 4; break;
        case 1: src = y;  dst = (uint2*)g_y;  n4 = M * D / 4; break;
        case 2: src = wq; dst = (uint2*)g_wq; n4 = D * D / 4; break;
        case 3: src = wk; dst = (uint2*)g_wk; n4 = D * D / 4; break;
        case 4: src = wv; dst = (uint2*)g_wv; n4 = D * D / 4; break;
        default: src = wo; dst = (uint2*)g_wo; n4 = D * D / 4; break;
    }
    for (int i = blockIdx.x * blockDim.x + threadIdx.x; i < n4;
         i += gridDim.x * blockDim.x) {
        float4 v = src[i];
        __half2 h01 = __floats2half2_rn(v.x, v.y);
        __half2 h23 = __floats2half2_rn(v.z, v.w);
        uint2 u;
        u.x = *reinterpret_cast<unsigned*>(&h01);
        u.y = *reinterpret_cast<unsigned*>(&h23);
        dst[i] = u;
    }
}

// ---------------------------------------------------------------------------
// GEMM: C = A[.,1024] @ W[1024,1024]^T, fp16 mma, cp.async 2-stage pipeline.
// Block 128x128, BK=64 halfs, 256 thr, 8 warps (4m x 2n), warp tile 32x64.
// All fragments via ldmatrix.x4. mode 0: f32 row-major; mode 1: head-split f16.
// ---------------------------------------------------------------------------
constexpr int GSTRIDE = 72;                   // halfs per smem row (64 + 8 pad)
constexpr int GT = 128 * GSTRIDE;             // halfs per (matrix,stage)
constexpr int GEMM_SMEM = 4 * GT * 2;         // 73728 B

__device__ __forceinline__
void gemm_body(const __half* __restrict__ A, const __half* __restrict__ W,
               void* __restrict__ Cout, int mode, int bx, int by)
{
    extern __shared__ __half smh[];
    const int tid    = threadIdx.x;
    const int lane   = tid & 31;
    const int warp   = tid >> 5;
    const int warp_m = warp >> 1;    // 0..3
    const int warp_n = warp & 1;     // 0..1
    const int m0 = by * 128;
    const int n0 = bx * 128;
    const int lr = lane >> 2;        // 0..7
    const int lc = lane & 3;         // 0..3
    const int t8 = lane >> 3;        // ldmatrix tile id 0..3
    const int rI = lane & 7;         // row within tile

    // ldmatrix source offsets (in halfs)
    // A tiles per (mt,ks): t0=[m0..7,k0..7] t1=[m8..15,k0..7] t2=[m0..7,k8..15] t3=[m8..15,k8..15]
    const int aOff = (warp_m * 32 + (t8 & 1) * 8 + rI) * GSTRIDE + (t8 >> 1) * 8;
    // W tiles per (nt2,ks): t0=[n0..7,k0..7] t1=[n0..7,k8..15] t2=[n8..15,k0..7] t3=[n8..15,k8..15]
    const int wOff = (warp_n * 64 + (t8 >> 1) * 8 + rI) * GSTRIDE + (t8 & 1) * 8;

    float acc[2][8][4];
#pragma unroll
    for (int i = 0; i < 2; i++)
#pragma unroll
        for (int j = 0; j < 8; j++)
#pragma unroll
            for (int t = 0; t < 4; t++) acc[i][j][t] = 0.f;

    auto load_stage = [&](int kc, __half* As, __half* Ws) {
        const __half* Ap = A + (size_t)m0 * D + kc * 64;
        const __half* Wp = W + (size_t)n0 * D + kc * 64;
#pragma unroll
        for (int t = 0; t < 4; t++) {
            int idx = tid + 256 * t;     // 0..1023
            int row = idx >> 3;
            int seg = idx & 7;           // 8 halfs = 16B
            cp16(As + row * GSTRIDE + seg * 8, Ap + (size_t)row * D + seg * 8);
        }
#pragma unroll
        for (int t = 0; t < 4; t++) {
            int idx = tid + 256 * t;
            int row = idx >> 3;
            int seg = idx & 7;
            cp16(Ws + row * GSTRIDE + seg * 8, Wp + (size_t)row * D + seg * 8);
        }
    };

    load_stage(0, smh, smh + 2 * GT);
    cp_commit();

    for (int kt = 0; kt < 16; kt++) {
        const int s = kt & 1;
        if (kt < 15) {
            load_stage(kt + 1, smh + (s ^ 1) * GT, smh + 2 * GT + (s ^ 1) * GT);
            cp_commit();
            cp_wait1();
        } else {
            cp_wait0();
        }
        __syncthreads();

        const __half* As = smh + s * GT;
        const __half* Ws = smh + 2 * GT + s * GT;

#pragma unroll
        for (int ks = 0; ks < 4; ks++) {
            unsigned a[2][4];
#pragma unroll
            for (int mt = 0; mt < 2; mt++)
                ldm_x4(a[mt], smem_u32(As + aOff + mt * (16 * GSTRIDE) + ks * 16));
#pragma unroll
            for (int nt2 = 0; nt2 < 4; nt2++) {
                unsigned b[4];
                ldm_x4(b, smem_u32(Ws + wOff + nt2 * (16 * GSTRIDE) + ks * 16));
#pragma unroll
                for (int mt = 0; mt < 2; mt++) {
                    mma16(acc[mt][2 * nt2],     a[mt][0], a[mt][1], a[mt][2], a[mt][3], b[0], b[1]);
                    mma16(acc[mt][2 * nt2 + 1], a[mt][0], a[mt][1], a[mt][2], a[mt][3], b[2], b[3]);
                }
            }
        }
        __syncthreads();
    }

#pragma unroll
    for (int mt = 0; mt < 2; mt++) {
#pragma unroll
        for (int nt = 0; nt < 8; nt++) {
            int rA = m0 + warp_m * 32 + mt * 16 + lr;
            int cA = n0 + warp_n * 64 + nt * 8 + 2 * lc;
#pragma unroll
            for (int half_i = 0; half_i < 2; half_i++) {
                int m = rA + half_i * 8;
                float v0 = acc[mt][nt][half_i * 2 + 0];
                float v1 = acc[mt][nt][half_i * 2 + 1];
                if (mode == 0) {
                    *(float2*)((float*)Cout + (size_t)m * D + cA) = make_float2(v0, v1);
                } else {
                    int bb = m >> 11;
                    int ss = m & (S - 1);
                    int hh = cA >> 6;
                    int dh = cA & (DH - 1);
                    __half* dst = (__half*)Cout + (((size_t)(bb * H + hh) * S + ss) * DH + dh);
                    *(__half2*)dst = __floats2half2_rn(v0, v1);
                }
            }
        }
    }
}

__global__ __launch_bounds__(256, 2)
void qkv_gemm()
{
    const __half* A; const __half* W; __half* C;
    if (blockIdx.z == 0)      { A = g_y; W = g_wq; C = g_q; }
    else if (blockIdx.z == 1) { A = g_x; W = g_wk; C = g_k; }
    else                      { A = g_x; W = g_wv; C = g_v; }
    gemm_body(A, W, C, 1, blockIdx.x, blockIdx.y);
}

__global__ __launch_bounds__(256, 2)
void o_gemm(float* __restrict__ Out)
{
    gemm_body(g_att, g_wo, Out, 0, blockIdx.x, blockIdx.y);
}

// ---------------------------------------------------------------------------
// Flash attention, naive softmax, fp16 mma, cp.async double-buffered K/V.
// CTA = 128 q-rows of one (b,h), 256 thr / 8 warps (16 rows each), k-tile 64.
// K B-frags via ldmatrix.x4; P kept entirely in registers (S C-frag layout ==
// PV A-frag layout); V frags via ldmatrix.x4.trans.
// ---------------------------------------------------------------------------
constexpr int KST = 64 * 72;     // halfs per K/V stage
constexpr int ATTN_SMEM = (4 * KST + 128 * 72) * 2;   // 55296 B

__global__ __launch_bounds__(256, 2)
void flash_attn(const float* __restrict__ mask)
{
    extern __shared__ __half smh[];
    __half* Ks2 = smh;               // 2 stages of 64x72
    __half* Vs2 = smh + 2 * KST;     // 2 stages of 64x72
    __half* Qs  = smh + 4 * KST;     // 128 x 72 (Q staging only)

    const int tid  = threadIdx.x;
    const int lane = tid & 31;
    const int warp = tid >> 5;
    const int lr = lane >> 2;      // 0..7
    const int lc = lane & 3;       // 0..3
    const int t8 = lane >> 3;      // ldmatrix tile id
    const int rI = lane & 7;
    const int bh = blockIdx.y;
    const int qb = blockIdx.x * 128;
    const int mnz = g_mask_nz;     // uniform per launch

    const __half* qp    = g_q + ((size_t)bh * S + qb) * DH;
    const __half* kbase = g_k + (size_t)bh * S * DH;
    const __half* vbase = g_v + (size_t)bh * S * DH;

    // K ldmatrix offset: tiles per (nt2,ks): t0=[n0..7,k0..7] t1=[n0..7,k8..15]
    //                                        t2=[n8..15,k0..7] t3=[n8..15,k8..15]
    const int kOff = ((t8 >> 1) * 8 + rI) * 72 + (t8 & 1) * 8;

    auto kv_load = [&](int kb, __half* Kd, __half* Vd) {
#pragma unroll
        for (int t = 0; t < 2; t++) {
            int idx = tid + 256 * t;   // 0..511
            int row = idx >> 3;        // 0..63
            int seg = idx & 7;
            cp16(Kd + row * 72 + seg * 8, kbase + (size_t)(kb + row) * DH + seg * 8);
        }
#pragma unroll
        for (int t = 0; t < 2; t++) {
            int idx = tid + 256 * t;
            int row = idx >> 3;
            int seg = idx & 7;
            cp16(Vd + row * 72 + seg * 8, vbase + (size_t)(kb + row) * DH + seg * 8);
        }
    };

    // Stage Q (128 x 64 halfs)
#pragma unroll
    for (int t = 0; t < 4; t++) {
        int idx = tid + 256 * t;       // 0..1023
        int row = idx >> 3;            // 0..127
        int seg = idx & 7;
        cp16(&Qs[row * 72 + seg * 8], qp + (size_t)row * DH + seg * 8);
    }
    cp_commit();
    kv_load(0, Ks2, Vs2);
    cp_commit();
    cp_wait1();          // Q complete (KV0 may still be in flight)
    __syncthreads();

    const int r0 = warp * 16 + lr;       // warp-local q row (of 128)

    // Q fragments in registers for the whole loop (DH=64 -> 4 k16 steps)
    unsigned qf[4][4];
#pragma unroll
    for (int ks = 0; ks < 4; ks++) {
        const int kc = ks * 16 + 2 * lc;
        qf[ks][0] = *(const unsigned*)&Qs[r0 * 72 + kc];
        qf[ks][1] = *(const unsigned*)&Qs[(r0 + 8) * 72 + kc];
        qf[ks][2] = *(const unsigned*)&Qs[r0 * 72 + kc + 8];
        qf[ks][3] = *(const unsigned*)&Qs[(r0 + 8) * 72 + kc + 8];
    }

    float accO[8][4];
#pragma unroll
    for (int i = 0; i < 8; i++)
#pragma unroll
        for (int t = 0; t < 4; t++) accO[i][t] = 0.f;
    float rs0 = 0.f, rs1 = 0.f;

    for (int kt = 0; kt < S / 64; kt++) {
        const int s = kt & 1;
        if (kt < S / 64 - 1) {
            kv_load((kt + 1) * 64, Ks2 + (s ^ 1) * KST, Vs2 + (s ^ 1) * KST);
            cp_commit();
            cp_wait1();     // KV[kt] done, KV[kt+1] in flight
        } else {
            cp_wait0();
        }
        __syncthreads();    // KV[kt] visible; prior-stage reads done

        const __half* Ks = Ks2 + s * KST;
        const __half* Vs = Vs2 + s * KST;
        const int kb = kt * 64;

        // S = Q K^T  (warp: 16 x 64), K B-frags via ldmatrix.x4
        float sAcc[8][4];
#pragma unroll
        for (int i = 0; i < 8; i++)
#pragma unroll
            for (int t = 0; t < 4; t++) sAcc[i][t] = 0.f;
#pragma unroll
        for (int ks = 0; ks < 4; ks++) {
#pragma unroll
            for (int nt2 = 0; nt2 < 4; nt2++) {
                unsigned b[4];
                ldm_x4(b, smem_u32(Ks + kOff + nt2 * (16 * 72) + ks * 16));
                mma16(sAcc[2 * nt2],     qf[ks][0], qf[ks][1], qf[ks][2], qf[ks][3], b[0], b[1]);
                mma16(sAcc[2 * nt2 + 1], qf[ks][0], qf[ks][1], qf[ks][2], qf[ks][3], b[2], b[3]);
            }
        }

        // exp(scale + mask) -> P directly in registers (half2 packs).
        unsigned ph0[8], ph1[8];
#pragma unroll
        for (int nt = 0; nt < 8; nt++) {
            int col = nt * 8 + 2 * lc;
            float2 m0v = make_float2(0.f, 0.f);
            float2 m1v = make_float2(0.f, 0.f);
            if (mnz) {
                m0v = *(const float2*)(mask + (size_t)(qb + r0) * S + kb + col);
                m1v = *(const float2*)(mask + (size_t)(qb + r0 + 8) * S + kb + col);
            }
            float e00 = __expf(fmaf(sAcc[nt][0], 0.125f, m0v.x));
            float e01 = __expf(fmaf(sAcc[nt][1], 0.125f, m0v.y));
            float e10 = __expf(fmaf(sAcc[nt][2], 0.125f, m1v.x));
            float e11 = __expf(fmaf(sAcc[nt][3], 0.125f, m1v.y));
            rs0 += e00 + e01;
            rs1 += e10 + e11;
            __half2 h0 = __floats2half2_rn(e00, e01);
            __half2 h1 = __floats2half2_rn(e10, e11);
            ph0[nt] = *reinterpret_cast<unsigned*>(&h0);
            ph1[nt] = *reinterpret_cast<unsigned*>(&h1);
        }

        // O += P V  (P A-frags straight from registers; V via ldmatrix.trans)
#pragma unroll
        for (int ktc = 0; ktc < 4; ktc++) {
            unsigned a0 = ph0[2 * ktc];
            unsigned a1 = ph1[2 * ktc];
            unsigned a2 = ph0[2 * ktc + 1];
            unsigned a3 = ph1[2 * ktc + 1];
#pragma unroll
            for (int dtp = 0; dtp < 4; dtp++) {
                const int grp = lane >> 3;
                const int ii  = lane & 7;
                const int vrow = ktc * 16 + ((grp & 1) << 3) + ii;
                const int vcol = (dtp * 2 + (grp >> 1)) * 8;
                uint32_t addr = smem_u32(&Vs[vrow * 72 + vcol]);
                unsigned v0, v1, v2, v3;
                asm volatile(
                    "ldmatrix.sync.aligned.m8n8.x4.trans.shared.b16 {%0,%1,%2,%3}, [%4];"
                    : "=r"(v0), "=r"(v1), "=r"(v2), "=r"(v3) : "r"(addr));
                mma16(accO[dtp * 2],     a0, a1, a2, a3, v0, v1);
                mma16(accO[dtp * 2 + 1], a0, a1, a2, a3, v2, v3);
            }
        }
        __syncthreads();    // stage-s reads done before next prefetch overwrites
    }

    // full row sums (cols of a row live in the 4 lanes of a quad)
    rs0 += __shfl_xor_sync(0xffffffffu, rs0, 1);
    rs0 += __shfl_xor_sync(0xffffffffu, rs0, 2);
    rs1 += __shfl_xor_sync(0xffffffffu, rs1, 1);
    rs1 += __shfl_xor_sync(0xffffffffu, rs1, 2);
    float inv0 = 1.f / (rs0 + 1e-10f);
    float inv1 = 1.f / (rs1 + 1e-10f);

    const int bb = bh >> 4;        // bh / H
    const int hh = bh & (H - 1);
    const int mrow0 = qb + r0;
#pragma unroll
    for (int dt = 0; dt < 8; dt++) {
        int col = hh * DH + dt * 8 + 2 * lc;
        __half* dst0 = g_att + ((size_t)(bb * S + mrow0)) * D + col;
        __half* dst1 = g_att + ((size_t)(bb * S + mrow0 + 8)) * D + col;
        *(__half2*)dst0 = __floats2half2_rn(accO[dt][0] * inv0, accO[dt][1] * inv0);
        *(__half2*)dst1 = __floats2half2_rn(accO[dt][2] * inv1, accO[dt][3] * inv1);
    }
}

// ---------------------------------------------------------------------------
extern "C" void kernel_launch(void* const* d_in, const int* in_sizes, int n_in,
                              void* d_out, int out_size)
{
    (void)in_sizes; (void)n_in; (void)out_size;
    const float* x    = (const float*)d_in[0];
    const float* y    = (const float*)d_in[1];
    const float* mask = (const float*)d_in[2];
    const float* Wq   = (const float*)d_in[3];
    const float* Wk   = (const float*)d_in[4];
    const float* Wv   = (const float*)d_in[5];
    const float* Wo   = (const float*)d_in[6];
    float* out = (float*)d_out;

    static bool attr_set = false;
    if (!attr_set) {
        cudaFuncSetAttribute(flash_attn, cudaFuncAttributeMaxDynamicSharedMemorySize,
                             ATTN_SMEM);
        cudaFuncSetAttribute(qkv_gemm, cudaFuncAttributeMaxDynamicSharedMemorySize,
                             GEMM_SMEM);
        cudaFuncSetAttribute(o_gemm, cudaFuncAttributeMaxDynamicSharedMemorySize,
                             GEMM_SMEM);
        attr_set = true;
    }

    // clear mask flag (memset node; graph-capturable), then cvt + mask check
    int* flag_ptr;
    cudaGetSymbolAddress((void**)&flag_ptr, g_mask_nz);
    cudaMemsetAsync(flag_ptr, 0, sizeof(int));

    cvt_all<<<dim3(512, 1, 7), 256>>>((const float4*)x,  (const float4*)y,
                                      (const float4*)Wq, (const float4*)Wk,
                                      (const float4*)Wv, (const float4*)Wo,
                                      (const float4*)mask);

    qkv_gemm<<<dim3(D / 128, M / 128, 3), 256, GEMM_SMEM>>>();
    flash_attn<<<dim3(S / 128, B * H), 256, ATTN_SMEM>>>(mask);
    o_gemm<<<dim3(D / 128, M / 128), 256, GEMM_SMEM>>>(out);
}